// round 4
// baseline (speedup 1.0000x reference)
#include <cuda_runtime.h>
#include <cuda_bf16.h>
#include <cstdint>
#include <cmath>

#define DIV_UP(a, b) (((a) + (b) - 1) / (b))

// Scratch for MLP ping-pong (B*Q*D = 307200 floats needed; headroom allocated)
__device__ __align__(16) float g_mlp_a[1 << 20];
__device__ __align__(16) float g_mlp_b[1 << 20];

// ============================================================================
// helpers
// ============================================================================
__device__ __forceinline__ uint32_t smem_to_u32(const void* smem_ptr) {
    uint32_t addr;
    asm("{ .reg .u64 tmp; cvta.to.shared.u64 tmp, %1; cvt.u32.u64 %0, tmp; }"
        : "=r"(addr) : "l"(smem_ptr));
    return addr;
}

__device__ __forceinline__ void ldmatrix_x4(uint32_t* r, uint32_t addr) {
    asm volatile("ldmatrix.sync.aligned.m8n8.x4.shared.b16 {%0,%1,%2,%3}, [%4];"
                 : "=r"(r[0]), "=r"(r[1]), "=r"(r[2]), "=r"(r[3]) : "r"(addr));
}

// D = A(bf16) * B(bf16)^T + D, m16n8k16
__device__ __forceinline__ void mma_bf16(float* c, const uint32_t* a,
                                         const uint32_t* b) {
    asm volatile(
        "mma.sync.aligned.m16n8k16.row.col.f32.bf16.bf16.f32 "
        "{%0,%1,%2,%3}, {%4,%5,%6,%7}, {%8,%9}, {%0,%1,%2,%3};"
        : "+f"(c[0]), "+f"(c[1]), "+f"(c[2]), "+f"(c[3])
        : "r"(a[0]), "r"(a[1]), "r"(a[2]), "r"(a[3]), "r"(b[0]), "r"(b[1]));
}

// split fp32 pair into packed bf16x2 hi and lo planes
__device__ __forceinline__ void split2(float x, float y, uint32_t& hi, uint32_t& lo) {
    __nv_bfloat16 hx = __float2bfloat16(x);
    __nv_bfloat16 hy = __float2bfloat16(y);
    __nv_bfloat16 lx = __float2bfloat16(x - __bfloat162float(hx));
    __nv_bfloat16 ly = __float2bfloat16(y - __bfloat162float(hy));
    hi = (uint32_t)__bfloat16_as_ushort(hx) | ((uint32_t)__bfloat16_as_ushort(hy) << 16);
    lo = (uint32_t)__bfloat16_as_ushort(lx) | ((uint32_t)__bfloat16_as_ushort(ly) << 16);
}

// ============================================================================
// MLP layer: Y[M,N] = act(X[M,K] @ W[N,K]^T + bias). 32x32 tiles, BK=64.
// ============================================================================
template <int RELU>
__global__ void __launch_bounds__(256)
mlp_kernel(const float* __restrict__ X, const float* __restrict__ Wm,
           const float* __restrict__ bias, float* __restrict__ Y,
           int M, int K, int N) {
    constexpr int BM = 32, BN = 32, BK = 64;
    __shared__ __align__(16) float Xs[BK][BM + 1];
    __shared__ __align__(16) float Ws[BK][BN + 1];

    const int m0 = blockIdx.x * BM;
    const int n0 = blockIdx.y * BN;
    const int tid = threadIdx.x;
    const int ti = tid & 15;
    const int tj = tid >> 4;

    float acc[2][2] = {};

    for (int k0 = 0; k0 < K; k0 += BK) {
        #pragma unroll
        for (int i = 0; i < 2; ++i) {   // X tile 32 x 64 -> Xs[k][m]
            int quad = tid + i * 256;
            int r = quad >> 4, c4 = (quad & 15) * 4;
            float4 v = make_float4(0.f, 0.f, 0.f, 0.f);
            if (m0 + r < M)
                v = *reinterpret_cast<const float4*>(X + (long)(m0 + r) * K + k0 + c4);
            Xs[c4 + 0][r] = v.x; Xs[c4 + 1][r] = v.y;
            Xs[c4 + 2][r] = v.z; Xs[c4 + 3][r] = v.w;
        }
        #pragma unroll
        for (int i = 0; i < 2; ++i) {   // W tile 32 x 64 -> Ws[k][n]
            int quad = tid + i * 256;
            int r = quad >> 4, c4 = (quad & 15) * 4;
            float4 v = make_float4(0.f, 0.f, 0.f, 0.f);
            if (n0 + r < N)
                v = *reinterpret_cast<const float4*>(Wm + (long)(n0 + r) * K + k0 + c4);
            Ws[c4 + 0][r] = v.x; Ws[c4 + 1][r] = v.y;
            Ws[c4 + 2][r] = v.z; Ws[c4 + 3][r] = v.w;
        }
        __syncthreads();
        #pragma unroll
        for (int k = 0; k < BK; ++k) {
            float a0 = Xs[k][ti * 2 + 0];
            float a1 = Xs[k][ti * 2 + 1];
            float b0 = Ws[k][tj * 2 + 0];
            float b1 = Ws[k][tj * 2 + 1];
            acc[0][0] = fmaf(a0, b0, acc[0][0]);
            acc[0][1] = fmaf(a0, b1, acc[0][1]);
            acc[1][0] = fmaf(a1, b0, acc[1][0]);
            acc[1][1] = fmaf(a1, b1, acc[1][1]);
        }
        __syncthreads();
    }

    #pragma unroll
    for (int s = 0; s < 2; ++s) {
        int m = m0 + ti * 2 + s;
        if (m >= M) continue;
        #pragma unroll
        for (int j = 0; j < 2; ++j) {
            int n = n0 + tj * 2 + j;
            if (n >= N) continue;
            float v = acc[s][j] + bias[n];
            if (RELU) v = fmaxf(v, 0.f);
            Y[(long)m * N + n] = v;
        }
    }
}

// ============================================================================
// Logits GEMM via mma.sync bf16 (hi/lo split) + fused float2 atomic scatter.
// CTA tile: 128(f) x 160(q). 8 warps as 4(m) x 2(n); warp tile 32x80.
// QTILE=160 -> only 2 q-tiles: fv loaded+converted 2x instead of 5x.
// ============================================================================
constexpr int FTILE = 128;
constexpr int QTILE = 160;
constexpr int KC    = 32;
constexpr int LDSA  = KC + 8;   // bf16 elements per row (padding kills conflicts)

__global__ void __launch_bounds__(256)
logits_mma_kernel(const float* __restrict__ fv,   // [B*F, D]
                  const int* __restrict__ fidx,   // [B*F, 3]
                  const float* __restrict__ qf,   // [B*Q, D]
                  float* __restrict__ out,
                  const int* __restrict__ width_ptr, int width_imm,
                  int F, int Q, int D, long HWQ) {
    __shared__ __align__(16) __nv_bfloat16 As_hi[FTILE * LDSA];
    __shared__ __align__(16) __nv_bfloat16 As_lo[FTILE * LDSA];
    __shared__ __align__(16) __nv_bfloat16 Bs_hi[QTILE * LDSA];
    __shared__ __align__(16) __nv_bfloat16 Bs_lo[QTILE * LDSA];

    const int tid  = threadIdx.x;
    const int wid  = tid >> 5;
    const int lane = tid & 31;
    const int b  = blockIdx.z;
    const int f0 = blockIdx.x * FTILE;
    const int q0 = blockIdx.y * QTILE;

    const int warp_m = (wid & 3) * 32;
    const int warp_n = (wid >> 2) * 80;

    const float* Abase = fv + ((long)b * F + f0) * D;
    const float* Bbase = qf + ((long)b * Q) * D;

    float c[2][10][4] = {};   // [m-frag 16][n-frag 8][regs] = 80 floats

    const uint32_t as_hi = smem_to_u32(As_hi);
    const uint32_t as_lo = smem_to_u32(As_lo);
    const uint32_t bs_hi = smem_to_u32(Bs_hi);
    const uint32_t bs_lo = smem_to_u32(Bs_lo);

    for (int k0 = 0; k0 < D; k0 += KC) {
        // ---- load + split A tile: 128 x 32 fp32 (1024 float4, 4/thread) ----
        #pragma unroll
        for (int i = 0; i < 4; ++i) {
            int quad = tid + i * 256;
            int row = quad >> 3;            // 0..127
            int c4  = (quad & 7) << 2;      // 0..28
            float4 v = make_float4(0.f, 0.f, 0.f, 0.f);
            if (f0 + row < F)
                v = *reinterpret_cast<const float4*>(Abase + (long)row * D + k0 + c4);
            uint32_t h0, l0, h1, l1;
            split2(v.x, v.y, h0, l0);
            split2(v.z, v.w, h1, l1);
            int off = row * LDSA + c4;
            *reinterpret_cast<uint2*>(&As_hi[off]) = make_uint2(h0, h1);
            *reinterpret_cast<uint2*>(&As_lo[off]) = make_uint2(l0, l1);
        }
        // ---- load + split B tile: 160 x 32 fp32 (1280 float4, 5/thread) ----
        #pragma unroll
        for (int i = 0; i < 5; ++i) {
            int quad = tid + i * 256;
            int row = quad >> 3;            // 0..159
            int c4  = (quad & 7) << 2;
            float4 v = make_float4(0.f, 0.f, 0.f, 0.f);
            if (q0 + row < Q)
                v = *reinterpret_cast<const float4*>(Bbase + (long)(q0 + row) * D + k0 + c4);
            uint32_t h0, l0, h1, l1;
            split2(v.x, v.y, h0, l0);
            split2(v.z, v.w, h1, l1);
            int off = row * LDSA + c4;
            *reinterpret_cast<uint2*>(&Bs_hi[off]) = make_uint2(h0, h1);
            *reinterpret_cast<uint2*>(&Bs_lo[off]) = make_uint2(l0, l1);
        }
        __syncthreads();

        // ---- mainloop: 2 k16 steps per chunk ----
        #pragma unroll
        for (int kk = 0; kk < KC; kk += 16) {
            uint32_t ah[2][4], al[2][4];
            #pragma unroll
            for (int mi = 0; mi < 2; ++mi) {
                int row = warp_m + mi * 16 + (lane & 15);
                int col = kk + ((lane >> 4) << 3);
                uint32_t addr = (uint32_t)((row * LDSA + col) * 2);
                ldmatrix_x4(ah[mi], as_hi + addr);
                ldmatrix_x4(al[mi], as_lo + addr);
            }
            uint32_t bh[10][2], bl[10][2];
            #pragma unroll
            for (int nb = 0; nb < 5; ++nb) {
                // x4 ldmatrix covers 16 n-rows x 16 k
                int row = warp_n + nb * 16 + ((lane & 16) >> 1) + (lane & 7);
                int col = kk + ((lane >> 3) & 1) * 8;
                uint32_t addr = (uint32_t)((row * LDSA + col) * 2);
                uint32_t rh[4], rl[4];
                ldmatrix_x4(rh, bs_hi + addr);
                ldmatrix_x4(rl, bs_lo + addr);
                bh[nb * 2 + 0][0] = rh[0]; bh[nb * 2 + 0][1] = rh[1];
                bh[nb * 2 + 1][0] = rh[2]; bh[nb * 2 + 1][1] = rh[3];
                bl[nb * 2 + 0][0] = rl[0]; bl[nb * 2 + 0][1] = rl[1];
                bl[nb * 2 + 1][0] = rl[2]; bl[nb * 2 + 1][1] = rl[3];
            }
            #pragma unroll
            for (int mi = 0; mi < 2; ++mi) {
                #pragma unroll
                for (int ni = 0; ni < 10; ++ni) {
                    mma_bf16(c[mi][ni], ah[mi], bh[ni]);   // hi*hi
                    mma_bf16(c[mi][ni], ah[mi], bl[ni]);   // hi*lo
                    mma_bf16(c[mi][ni], al[mi], bh[ni]);   // lo*hi
                }
            }
        }
        __syncthreads();
    }

    // ---- epilogue: scatter-add with float2 atomics ----
    const int Wd = width_ptr ? *width_ptr : width_imm;
    const long nb0 = (long)b * F + f0;

    #pragma unroll
    for (int mi = 0; mi < 2; ++mi) {
        #pragma unroll
        for (int half = 0; half < 2; ++half) {   // +0 / +8 rows within m16
            int row = warp_m + mi * 16 + half * 8 + (lane >> 2);
            int f = f0 + row;
            if (f >= F) continue;
            long n = nb0 + row;
            int hh = fidx[3 * n + 1];
            int ww = fidx[3 * n + 2];
            long obase = (long)b * HWQ + ((long)hh * Wd + ww) * (long)Q;
            #pragma unroll
            for (int ni = 0; ni < 10; ++ni) {
                int q = q0 + warp_n + ni * 8 + 2 * (lane & 3);
                float v0 = c[mi][ni][half * 2 + 0];
                float v1 = c[mi][ni][half * 2 + 1];
                if (q + 1 < Q) {
                    atomicAdd(reinterpret_cast<float2*>(out + obase + q),
                              make_float2(v0, v1));
                } else if (q < Q) {
                    atomicAdd(out + obase + q, v0);
                }
            }
        }
    }
}

// ---------------------------------------------------------------------------
static int isqrt_host(long v) {
    int r = (int)(sqrt((double)v) + 0.5);
    while ((long)r * r > v) --r;
    while ((long)(r + 1) * (r + 1) <= v) ++r;
    return r;
}

extern "C" void kernel_launch(void* const* d_in, const int* in_sizes, int n_in,
                              void* d_out, int out_size) {
    // Input order: queries, feature_values, feature_indices, query_batch_offsets,
    // feature_batch_offsets, height, width, W0,b0, W1,b1, W2,b2, W3,b3.
    const float* queries = (const float*)d_in[0];
    const float* fv      = (const float*)d_in[1];
    const int*   fidx    = (const int*)d_in[2];

    bool scalars_present = (n_in >= 15 && in_sizes[5] == 1 && in_sizes[6] == 1);
    int wbase = scalars_present ? 7 : 5;
    const int* width_ptr = scalars_present ? (const int*)d_in[6] : nullptr;

    const float* Wl[4];
    const float* bl[4];
    for (int i = 0; i < 4; ++i) {
        Wl[i] = (const float*)d_in[wbase + 2 * i];
        bl[i] = (const float*)d_in[wbase + 2 * i + 1];
    }

    const int D  = in_sizes[wbase + 1];       // len(b0)
    const int Mq = in_sizes[0] / D;           // B*Q
    const int B  = in_sizes[3] - 1;
    const int Q  = Mq / B;
    const int NF = in_sizes[1] / D;           // B*F
    const int F  = NF / B;
    const long HWQ = (long)out_size / B;      // H*W*Q
    const int width_imm = isqrt_host(HWQ / Q);

    float* buf0 = nullptr;
    float* buf1 = nullptr;
    cudaGetSymbolAddress((void**)&buf0, g_mlp_a);
    cudaGetSymbolAddress((void**)&buf1, g_mlp_b);

    // 1) Zero the output (poisoned by harness)
    cudaMemsetAsync(d_out, 0, (size_t)out_size * sizeof(float), 0);

    // 2) Query MLP: 3x (linear+relu), 1x linear
    {
        dim3 grid(DIV_UP(Mq, 32), DIV_UP(D, 32));
        mlp_kernel<1><<<grid, 256>>>(queries, Wl[0], bl[0], buf0, Mq, D, D);
        mlp_kernel<1><<<grid, 256>>>(buf0,    Wl[1], bl[1], buf1, Mq, D, D);
        mlp_kernel<1><<<grid, 256>>>(buf1,    Wl[2], bl[2], buf0, Mq, D, D);
        mlp_kernel<0><<<grid, 256>>>(buf0,    Wl[3], bl[3], buf1, Mq, D, D);
    }

    // 3) Logits GEMM (mma.sync bf16 split) fused with scatter-add
    {
        dim3 grid(DIV_UP(F, FTILE), DIV_UP(Q, QTILE), B);
        logits_mma_kernel<<<grid, 256>>>(fv, fidx, buf1, (float*)d_out,
                                         width_ptr, width_imm,
                                         F, Q, D, HWQ);
    }
}

// round 5
// speedup vs baseline: 1.0035x; 1.0035x over previous
#include <cuda_runtime.h>
#include <cuda_bf16.h>
#include <cstdint>
#include <cmath>

#define DIV_UP(a, b) (((a) + (b) - 1) / (b))

// Scratch (static device allocations — the only legal kind here)
__device__ __align__(16) float g_mlp_a[1 << 20];            // 4 MB
__device__ __align__(16) float g_mlp_b[1 << 20];            // 4 MB
__device__ __align__(16) __nv_bfloat16 g_fv_hi[1 << 24];    // 33.5 MB
__device__ __align__(16) __nv_bfloat16 g_fv_lo[1 << 24];    // 33.5 MB
__device__ __align__(16) __nv_bfloat16 g_q_hi[1 << 19];     // 1 MB
__device__ __align__(16) __nv_bfloat16 g_q_lo[1 << 19];     // 1 MB

// ============================================================================
// helpers
// ============================================================================
__device__ __forceinline__ uint32_t smem_to_u32(const void* smem_ptr) {
    uint32_t addr;
    asm("{ .reg .u64 tmp; cvta.to.shared.u64 tmp, %1; cvt.u32.u64 %0, tmp; }"
        : "=r"(addr) : "l"(smem_ptr));
    return addr;
}

__device__ __forceinline__ void ldmatrix_x4(uint32_t* r, uint32_t addr) {
    asm volatile("ldmatrix.sync.aligned.m8n8.x4.shared.b16 {%0,%1,%2,%3}, [%4];"
                 : "=r"(r[0]), "=r"(r[1]), "=r"(r[2]), "=r"(r[3]) : "r"(addr));
}

// D = A(bf16) * B(bf16)^T + D, m16n8k16
__device__ __forceinline__ void mma_bf16(float* c, const uint32_t* a,
                                         const uint32_t* b) {
    asm volatile(
        "mma.sync.aligned.m16n8k16.row.col.f32.bf16.bf16.f32 "
        "{%0,%1,%2,%3}, {%4,%5,%6,%7}, {%8,%9}, {%0,%1,%2,%3};"
        : "+f"(c[0]), "+f"(c[1]), "+f"(c[2]), "+f"(c[3])
        : "r"(a[0]), "r"(a[1]), "r"(a[2]), "r"(a[3]), "r"(b[0]), "r"(b[1]));
}

// split fp32 pair into packed bf16x2 hi and lo planes
__device__ __forceinline__ void split2(float x, float y, uint32_t& hi, uint32_t& lo) {
    __nv_bfloat16 hx = __float2bfloat16(x);
    __nv_bfloat16 hy = __float2bfloat16(y);
    __nv_bfloat16 lx = __float2bfloat16(x - __bfloat162float(hx));
    __nv_bfloat16 ly = __float2bfloat16(y - __bfloat162float(hy));
    hi = (uint32_t)__bfloat16_as_ushort(hx) | ((uint32_t)__bfloat16_as_ushort(hy) << 16);
    lo = (uint32_t)__bfloat16_as_ushort(lx) | ((uint32_t)__bfloat16_as_ushort(ly) << 16);
}

// ============================================================================
// fp32 -> bf16 hi/lo plane conversion (one pass, streaming)
// ============================================================================
__global__ void __launch_bounds__(256)
convert_split_kernel(const float* __restrict__ in,
                     __nv_bfloat16* __restrict__ hi,
                     __nv_bfloat16* __restrict__ lo, long n4) {
    long i = (long)blockIdx.x * blockDim.x + threadIdx.x;
    if (i >= n4) return;
    float4 v = reinterpret_cast<const float4*>(in)[i];
    uint32_t h0, l0, h1, l1;
    split2(v.x, v.y, h0, l0);
    split2(v.z, v.w, h1, l1);
    reinterpret_cast<uint2*>(hi)[i] = make_uint2(h0, h1);
    reinterpret_cast<uint2*>(lo)[i] = make_uint2(l0, l1);
}

// ============================================================================
// MLP layer: Y[M,N] = act(X[M,K] @ W[N,K]^T + bias). 32x32 tiles, BK=32 (R3).
// ============================================================================
template <int RELU>
__global__ void __launch_bounds__(256)
mlp_kernel(const float* __restrict__ X, const float* __restrict__ Wm,
           const float* __restrict__ bias, float* __restrict__ Y,
           int M, int K, int N) {
    constexpr int BM = 32, BN = 32, BK = 32;
    __shared__ __align__(16) float Xs[BK][BM + 1];
    __shared__ __align__(16) float Ws[BK][BN + 1];

    const int m0 = blockIdx.x * BM;
    const int n0 = blockIdx.y * BN;
    const int tid = threadIdx.x;
    const int ti = tid & 15;
    const int tj = tid >> 4;

    float acc[2][2] = {};

    for (int k0 = 0; k0 < K; k0 += BK) {
        {
            int r = tid >> 3, c4 = (tid & 7) * 4;
            float4 v = make_float4(0.f, 0.f, 0.f, 0.f);
            if (m0 + r < M)
                v = *reinterpret_cast<const float4*>(X + (long)(m0 + r) * K + k0 + c4);
            Xs[c4 + 0][r] = v.x; Xs[c4 + 1][r] = v.y;
            Xs[c4 + 2][r] = v.z; Xs[c4 + 3][r] = v.w;
        }
        {
            int r = tid >> 3, c4 = (tid & 7) * 4;
            float4 v = make_float4(0.f, 0.f, 0.f, 0.f);
            if (n0 + r < N)
                v = *reinterpret_cast<const float4*>(Wm + (long)(n0 + r) * K + k0 + c4);
            Ws[c4 + 0][r] = v.x; Ws[c4 + 1][r] = v.y;
            Ws[c4 + 2][r] = v.z; Ws[c4 + 3][r] = v.w;
        }
        __syncthreads();
        #pragma unroll
        for (int k = 0; k < BK; ++k) {
            float a0 = Xs[k][ti * 2 + 0];
            float a1 = Xs[k][ti * 2 + 1];
            float b0 = Ws[k][tj * 2 + 0];
            float b1 = Ws[k][tj * 2 + 1];
            acc[0][0] = fmaf(a0, b0, acc[0][0]);
            acc[0][1] = fmaf(a0, b1, acc[0][1]);
            acc[1][0] = fmaf(a1, b0, acc[1][0]);
            acc[1][1] = fmaf(a1, b1, acc[1][1]);
        }
        __syncthreads();
    }

    #pragma unroll
    for (int s = 0; s < 2; ++s) {
        int m = m0 + ti * 2 + s;
        if (m >= M) continue;
        #pragma unroll
        for (int j = 0; j < 2; ++j) {
            int n = n0 + tj * 2 + j;
            if (n >= N) continue;
            float v = acc[s][j] + bias[n];
            if (RELU) v = fmaxf(v, 0.f);
            Y[(long)m * N + n] = v;
        }
    }
}

// ============================================================================
// Logits GEMM: preconverted bf16 hi/lo planes, mma.sync, fused atomic scatter.
// CTA tile: 128(f) x 64(q), 8 warps 4x2, warp tile 32x32 (R3 register budget).
// Mainloop has ZERO conversion work: LDG(uint4) -> STS -> LDSM -> HMMA.
// ============================================================================
constexpr int FTILE = 128;
constexpr int QTILE = 64;
constexpr int KC    = 32;
constexpr int LDSA  = KC + 8;   // bf16 elems per smem row (pad kills conflicts)

__global__ void __launch_bounds__(256)
logits_mma_kernel(const __nv_bfloat16* __restrict__ fv_hi,   // [B*F, D]
                  const __nv_bfloat16* __restrict__ fv_lo,
                  const __nv_bfloat16* __restrict__ q_hi,    // [B*Q, D]
                  const __nv_bfloat16* __restrict__ q_lo,
                  const int* __restrict__ fidx,              // [B*F, 3]
                  float* __restrict__ out,
                  const int* __restrict__ width_ptr, int width_imm,
                  int F, int Q, int D, long HWQ) {
    __shared__ __align__(16) __nv_bfloat16 As_hi[FTILE * LDSA];
    __shared__ __align__(16) __nv_bfloat16 As_lo[FTILE * LDSA];
    __shared__ __align__(16) __nv_bfloat16 Bs_hi[QTILE * LDSA];
    __shared__ __align__(16) __nv_bfloat16 Bs_lo[QTILE * LDSA];

    const int tid  = threadIdx.x;
    const int wid  = tid >> 5;
    const int lane = tid & 31;
    const int b  = blockIdx.z;
    const int q0 = blockIdx.x * QTILE;   // q fastest -> A tiles reused in L2
    const int f0 = blockIdx.y * FTILE;

    const int warp_m = (wid & 3) * 32;
    const int warp_n = (wid >> 2) * 32;

    const long arow0 = (long)b * F + f0;
    const long brow0 = (long)b * Q;

    float c[2][4][4] = {};

    const uint32_t as_hi = smem_to_u32(As_hi);
    const uint32_t as_lo = smem_to_u32(As_lo);
    const uint32_t bs_hi = smem_to_u32(Bs_hi);
    const uint32_t bs_lo = smem_to_u32(Bs_lo);

    for (int k0 = 0; k0 < D; k0 += KC) {
        // ---- A tile: 128 rows x 32 bf16 per plane. 512 uint4/plane. ----
        #pragma unroll
        for (int i = 0; i < 2; ++i) {
            int idx = tid + i * 256;          // 0..511
            int row = idx >> 2;               // 0..127
            int seg = (idx & 3) * 8;          // bf16 offset 0,8,16,24
            long gofs = (arow0 + row) * D + k0 + seg;
            uint4 vh = *reinterpret_cast<const uint4*>(fv_hi + gofs);
            uint4 vl = *reinterpret_cast<const uint4*>(fv_lo + gofs);
            int off = row * LDSA + seg;
            *reinterpret_cast<uint4*>(&As_hi[off]) = vh;
            *reinterpret_cast<uint4*>(&As_lo[off]) = vl;
        }
        // ---- B tile: 64 rows x 32 bf16 per plane. 256 uint4/plane. ----
        {
            int idx = tid;                    // 0..255
            int row = idx >> 2;               // 0..63
            int seg = (idx & 3) * 8;
            // q rows beyond Q read in-bounds scratch garbage; results masked.
            int q = q0 + row;
            long gofs = (brow0 + (q < Q ? q : (Q - 1))) * D + k0 + seg;
            uint4 vh = *reinterpret_cast<const uint4*>(q_hi + gofs);
            uint4 vl = *reinterpret_cast<const uint4*>(q_lo + gofs);
            int off = row * LDSA + seg;
            *reinterpret_cast<uint4*>(&Bs_hi[off]) = vh;
            *reinterpret_cast<uint4*>(&Bs_lo[off]) = vl;
        }
        __syncthreads();

        // ---- mainloop: 2 k16 steps per chunk ----
        #pragma unroll
        for (int kk = 0; kk < KC; kk += 16) {
            uint32_t ah[2][4], al[2][4];
            #pragma unroll
            for (int mi = 0; mi < 2; ++mi) {
                int row = warp_m + mi * 16 + (lane & 15);
                int col = kk + ((lane >> 4) << 3);
                uint32_t addr = (uint32_t)((row * LDSA + col) * 2);
                ldmatrix_x4(ah[mi], as_hi + addr);
                ldmatrix_x4(al[mi], as_lo + addr);
            }
            uint32_t bh[4][2], bl[4][2];
            #pragma unroll
            for (int nb = 0; nb < 2; ++nb) {
                int row = warp_n + nb * 16 + ((lane & 16) >> 1) + (lane & 7);
                int col = kk + ((lane >> 3) & 1) * 8;
                uint32_t addr = (uint32_t)((row * LDSA + col) * 2);
                uint32_t rh[4], rl[4];
                ldmatrix_x4(rh, bs_hi + addr);
                ldmatrix_x4(rl, bs_lo + addr);
                bh[nb * 2 + 0][0] = rh[0]; bh[nb * 2 + 0][1] = rh[1];
                bh[nb * 2 + 1][0] = rh[2]; bh[nb * 2 + 1][1] = rh[3];
                bl[nb * 2 + 0][0] = rl[0]; bl[nb * 2 + 0][1] = rl[1];
                bl[nb * 2 + 1][0] = rl[2]; bl[nb * 2 + 1][1] = rl[3];
            }
            #pragma unroll
            for (int mi = 0; mi < 2; ++mi) {
                #pragma unroll
                for (int ni = 0; ni < 4; ++ni) {
                    mma_bf16(c[mi][ni], ah[mi], bh[ni]);   // hi*hi
                    mma_bf16(c[mi][ni], ah[mi], bl[ni]);   // hi*lo
                    mma_bf16(c[mi][ni], al[mi], bh[ni]);   // lo*hi
                }
            }
        }
        __syncthreads();
    }

    // ---- epilogue: scatter-add with float2 atomics ----
    const int Wd = width_ptr ? *width_ptr : width_imm;

    #pragma unroll
    for (int mi = 0; mi < 2; ++mi) {
        #pragma unroll
        for (int half = 0; half < 2; ++half) {
            int row = warp_m + mi * 16 + half * 8 + (lane >> 2);
            int f = f0 + row;
            if (f >= F) continue;
            long n = arow0 + row;
            int hh = fidx[3 * n + 1];
            int ww = fidx[3 * n + 2];
            long obase = (long)b * HWQ + ((long)hh * Wd + ww) * (long)Q;
            #pragma unroll
            for (int ni = 0; ni < 4; ++ni) {
                int q = q0 + warp_n + ni * 8 + 2 * (lane & 3);
                float v0 = c[mi][ni][half * 2 + 0];
                float v1 = c[mi][ni][half * 2 + 1];
                if (q + 1 < Q) {
                    atomicAdd(reinterpret_cast<float2*>(out + obase + q),
                              make_float2(v0, v1));
                } else if (q < Q) {
                    atomicAdd(out + obase + q, v0);
                }
            }
        }
    }
}

// ---------------------------------------------------------------------------
static int isqrt_host(long v) {
    int r = (int)(sqrt((double)v) + 0.5);
    while ((long)r * r > v) --r;
    while ((long)(r + 1) * (r + 1) <= v) ++r;
    return r;
}

extern "C" void kernel_launch(void* const* d_in, const int* in_sizes, int n_in,
                              void* d_out, int out_size) {
    // Input order: queries, feature_values, feature_indices, query_batch_offsets,
    // feature_batch_offsets, height, width, W0,b0, W1,b1, W2,b2, W3,b3.
    const float* queries = (const float*)d_in[0];
    const float* fv      = (const float*)d_in[1];
    const int*   fidx    = (const int*)d_in[2];

    bool scalars_present = (n_in >= 15 && in_sizes[5] == 1 && in_sizes[6] == 1);
    int wbase = scalars_present ? 7 : 5;
    const int* width_ptr = scalars_present ? (const int*)d_in[6] : nullptr;

    const float* Wl[4];
    const float* bl[4];
    for (int i = 0; i < 4; ++i) {
        Wl[i] = (const float*)d_in[wbase + 2 * i];
        bl[i] = (const float*)d_in[wbase + 2 * i + 1];
    }

    const int D  = in_sizes[wbase + 1];       // len(b0)
    const int Mq = in_sizes[0] / D;           // B*Q
    const int B  = in_sizes[3] - 1;
    const int Q  = Mq / B;
    const int NF = in_sizes[1] / D;           // B*F
    const int F  = NF / B;
    const long HWQ = (long)out_size / B;      // H*W*Q
    const int width_imm = isqrt_host(HWQ / Q);

    float *buf0 = nullptr, *buf1 = nullptr;
    __nv_bfloat16 *fv_hi = nullptr, *fv_lo = nullptr, *q_hi = nullptr, *q_lo = nullptr;
    cudaGetSymbolAddress((void**)&buf0, g_mlp_a);
    cudaGetSymbolAddress((void**)&buf1, g_mlp_b);
    cudaGetSymbolAddress((void**)&fv_hi, g_fv_hi);
    cudaGetSymbolAddress((void**)&fv_lo, g_fv_lo);
    cudaGetSymbolAddress((void**)&q_hi, g_q_hi);
    cudaGetSymbolAddress((void**)&q_lo, g_q_lo);

    // 1) Zero the output (poisoned by harness)
    cudaMemsetAsync(d_out, 0, (size_t)out_size * sizeof(float), 0);

    // 2) Convert fv -> bf16 hi/lo planes (once; used by logits mainloop)
    {
        long n4 = (long)NF * D / 4;
        convert_split_kernel<<<(int)DIV_UP(n4, 256L), 256>>>(fv, fv_hi, fv_lo, n4);
    }

    // 3) Query MLP: 3x (linear+relu), 1x linear
    {
        dim3 grid(DIV_UP(Mq, 32), DIV_UP(D, 32));
        mlp_kernel<1><<<grid, 256>>>(queries, Wl[0], bl[0], buf0, Mq, D, D);
        mlp_kernel<1><<<grid, 256>>>(buf0,    Wl[1], bl[1], buf1, Mq, D, D);
        mlp_kernel<1><<<grid, 256>>>(buf1,    Wl[2], bl[2], buf0, Mq, D, D);
        mlp_kernel<0><<<grid, 256>>>(buf0,    Wl[3], bl[3], buf1, Mq, D, D);
    }

    // 4) Convert MLP output -> bf16 hi/lo planes
    {
        long n4 = (long)Mq * D / 4;
        convert_split_kernel<<<(int)DIV_UP(n4, 256L), 256>>>(buf1, q_hi, q_lo, n4);
    }

    // 5) Logits GEMM (pure-MMA mainloop) fused with scatter-add
    {
        dim3 grid(DIV_UP(Q, QTILE), DIV_UP(F, FTILE), B);
        logits_mma_kernel<<<grid, 256>>>(fv_hi, fv_lo, q_hi, q_lo, fidx,
                                         (float*)d_out,
                                         width_ptr, width_imm,
                                         F, Q, D, HWQ);
    }
}

// round 6
// speedup vs baseline: 1.1931x; 1.1889x over previous
#include <cuda_runtime.h>
#include <cuda_bf16.h>
#include <cstdint>
#include <cmath>

#define DIV_UP(a, b) (((a) + (b) - 1) / (b))

// Scratch (static device allocations — the only legal kind here)
__device__ __align__(16) float g_mlp_a[1 << 20];            // 4 MB
__device__ __align__(16) float g_mlp_b[1 << 20];            // 4 MB
__device__ __align__(16) __nv_bfloat16 g_fv_hi[1 << 24];    // 33.5 MB
__device__ __align__(16) __nv_bfloat16 g_fv_lo[1 << 24];    // 33.5 MB
__device__ __align__(16) __nv_bfloat16 g_q_hi[1 << 19];     // 1 MB
__device__ __align__(16) __nv_bfloat16 g_q_lo[1 << 19];     // 1 MB

// ============================================================================
// helpers
// ============================================================================
__device__ __forceinline__ uint32_t smem_to_u32(const void* smem_ptr) {
    uint32_t addr;
    asm("{ .reg .u64 tmp; cvta.to.shared.u64 tmp, %1; cvt.u32.u64 %0, tmp; }"
        : "=r"(addr) : "l"(smem_ptr));
    return addr;
}

__device__ __forceinline__ void ldmatrix_x4(uint32_t* r, uint32_t addr) {
    asm volatile("ldmatrix.sync.aligned.m8n8.x4.shared.b16 {%0,%1,%2,%3}, [%4];"
                 : "=r"(r[0]), "=r"(r[1]), "=r"(r[2]), "=r"(r[3]) : "r"(addr));
}

// D = A(bf16) * B(bf16)^T + D, m16n8k16
__device__ __forceinline__ void mma_bf16(float* c, const uint32_t* a,
                                         const uint32_t* b) {
    asm volatile(
        "mma.sync.aligned.m16n8k16.row.col.f32.bf16.bf16.f32 "
        "{%0,%1,%2,%3}, {%4,%5,%6,%7}, {%8,%9}, {%0,%1,%2,%3};"
        : "+f"(c[0]), "+f"(c[1]), "+f"(c[2]), "+f"(c[3])
        : "r"(a[0]), "r"(a[1]), "r"(a[2]), "r"(a[3]), "r"(b[0]), "r"(b[1]));
}

__device__ __forceinline__ void cp16(uint32_t smem, const void* g) {
    asm volatile("cp.async.cg.shared.global [%0], [%1], 16;"
                 :: "r"(smem), "l"(g));
}

// split fp32 pair into packed bf16x2 hi and lo planes
__device__ __forceinline__ void split2(float x, float y, uint32_t& hi, uint32_t& lo) {
    __nv_bfloat16 hx = __float2bfloat16(x);
    __nv_bfloat16 hy = __float2bfloat16(y);
    __nv_bfloat16 lx = __float2bfloat16(x - __bfloat162float(hx));
    __nv_bfloat16 ly = __float2bfloat16(y - __bfloat162float(hy));
    hi = (uint32_t)__bfloat16_as_ushort(hx) | ((uint32_t)__bfloat16_as_ushort(hy) << 16);
    lo = (uint32_t)__bfloat16_as_ushort(lx) | ((uint32_t)__bfloat16_as_ushort(ly) << 16);
}

// ============================================================================
// fp32 -> bf16 hi/lo plane conversion (one pass, streaming)
// ============================================================================
__global__ void __launch_bounds__(256)
convert_split_kernel(const float* __restrict__ in,
                     __nv_bfloat16* __restrict__ hi,
                     __nv_bfloat16* __restrict__ lo, long n4) {
    long i = (long)blockIdx.x * blockDim.x + threadIdx.x;
    if (i >= n4) return;
    float4 v = reinterpret_cast<const float4*>(in)[i];
    uint32_t h0, l0, h1, l1;
    split2(v.x, v.y, h0, l0);
    split2(v.z, v.w, h1, l1);
    reinterpret_cast<uint2*>(hi)[i] = make_uint2(h0, h1);
    reinterpret_cast<uint2*>(lo)[i] = make_uint2(l0, l1);
}

// ============================================================================
// MLP layer: Y[M,N] = act(X[M,K] @ W[N,K]^T + bias). 32x32 tiles, BK=32.
// ============================================================================
template <int RELU>
__global__ void __launch_bounds__(256)
mlp_kernel(const float* __restrict__ X, const float* __restrict__ Wm,
           const float* __restrict__ bias, float* __restrict__ Y,
           int M, int K, int N) {
    constexpr int BM = 32, BN = 32, BK = 32;
    __shared__ __align__(16) float Xs[BK][BM + 1];
    __shared__ __align__(16) float Ws[BK][BN + 1];

    const int m0 = blockIdx.x * BM;
    const int n0 = blockIdx.y * BN;
    const int tid = threadIdx.x;
    const int ti = tid & 15;
    const int tj = tid >> 4;

    float acc[2][2] = {};

    for (int k0 = 0; k0 < K; k0 += BK) {
        {
            int r = tid >> 3, c4 = (tid & 7) * 4;
            float4 v = make_float4(0.f, 0.f, 0.f, 0.f);
            if (m0 + r < M)
                v = *reinterpret_cast<const float4*>(X + (long)(m0 + r) * K + k0 + c4);
            Xs[c4 + 0][r] = v.x; Xs[c4 + 1][r] = v.y;
            Xs[c4 + 2][r] = v.z; Xs[c4 + 3][r] = v.w;
        }
        {
            int r = tid >> 3, c4 = (tid & 7) * 4;
            float4 v = make_float4(0.f, 0.f, 0.f, 0.f);
            if (n0 + r < N)
                v = *reinterpret_cast<const float4*>(Wm + (long)(n0 + r) * K + k0 + c4);
            Ws[c4 + 0][r] = v.x; Ws[c4 + 1][r] = v.y;
            Ws[c4 + 2][r] = v.z; Ws[c4 + 3][r] = v.w;
        }
        __syncthreads();
        #pragma unroll
        for (int k = 0; k < BK; ++k) {
            float a0 = Xs[k][ti * 2 + 0];
            float a1 = Xs[k][ti * 2 + 1];
            float b0 = Ws[k][tj * 2 + 0];
            float b1 = Ws[k][tj * 2 + 1];
            acc[0][0] = fmaf(a0, b0, acc[0][0]);
            acc[0][1] = fmaf(a0, b1, acc[0][1]);
            acc[1][0] = fmaf(a1, b0, acc[1][0]);
            acc[1][1] = fmaf(a1, b1, acc[1][1]);
        }
        __syncthreads();
    }

    #pragma unroll
    for (int s = 0; s < 2; ++s) {
        int m = m0 + ti * 2 + s;
        if (m >= M) continue;
        #pragma unroll
        for (int j = 0; j < 2; ++j) {
            int n = n0 + tj * 2 + j;
            if (n >= N) continue;
            float v = acc[s][j] + bias[n];
            if (RELU) v = fmaxf(v, 0.f);
            Y[(long)m * N + n] = v;
        }
    }
}

// ============================================================================
// Logits GEMM: preconverted bf16 hi/lo planes, cp.async double-buffered,
// mma.sync mainloop, float4 vector-atomic scatter epilogue.
// CTA tile: 128(f) x 64(q), 8 warps 4x2, warp tile 32x32.
// ============================================================================
constexpr int FTILE = 128;
constexpr int QTILE = 64;
constexpr int KC    = 32;
constexpr int LDSA  = KC + 8;   // bf16 elems per smem row (80B stride, 16B-aligned)

// per-buffer byte offsets inside dynamic smem
constexpr int OFF_AHI = 0;
constexpr int OFF_ALO = OFF_AHI + FTILE * LDSA * 2;   // 10240
constexpr int OFF_BHI = OFF_ALO + FTILE * LDSA * 2;   // 20480
constexpr int OFF_BLO = OFF_BHI + QTILE * LDSA * 2;   // 25600
constexpr int BUF_SZ  = OFF_BLO + QTILE * LDSA * 2;   // 30720
constexpr int LOGITS_SMEM = 2 * BUF_SZ;               // 61440

__global__ void __launch_bounds__(256)
logits_mma_kernel(const __nv_bfloat16* __restrict__ fv_hi,   // [B*F, D]
                  const __nv_bfloat16* __restrict__ fv_lo,
                  const __nv_bfloat16* __restrict__ q_hi,    // [B*Q, D]
                  const __nv_bfloat16* __restrict__ q_lo,
                  const int* __restrict__ fidx,              // [B*F, 3]
                  float* __restrict__ out,
                  const int* __restrict__ width_ptr, int width_imm,
                  int F, int Q, int D, long HWQ) {
    extern __shared__ __align__(16) char smem[];
    const uint32_t sbase = smem_to_u32(smem);

    const int tid  = threadIdx.x;
    const int wid  = tid >> 5;
    const int lane = tid & 31;
    const int b  = blockIdx.z;
    const int q0 = blockIdx.x * QTILE;   // q fastest -> A tiles reused in L2
    const int f0 = blockIdx.y * FTILE;

    const int warp_m = (wid & 3) * 32;
    const int warp_n = (wid >> 2) * 32;

    const long arow0 = (long)b * F + f0;
    const long brow0 = (long)b * Q;

    float c[2][4][4] = {};

    const int nch = D / KC;

    // ---- async load of one K-chunk into buffer (c & 1) ----
    auto load_chunk = [&](int cc) {
        const int k0 = cc * KC;
        const uint32_t bb = sbase + (uint32_t)(cc & 1) * BUF_SZ;
        // A: 128 rows x 32 bf16 per plane = 512 x 16B per plane
        #pragma unroll
        for (int i = 0; i < 2; ++i) {
            int idx = tid + i * 256;
            int row = idx >> 2;
            int seg = (idx & 3) * 8;
            long g = (arow0 + row) * D + k0 + seg;
            uint32_t soff = (uint32_t)((row * LDSA + seg) * 2);
            cp16(bb + OFF_AHI + soff, fv_hi + g);
            cp16(bb + OFF_ALO + soff, fv_lo + g);
        }
        // B: 64 rows x 32 bf16 per plane = 256 x 16B per plane
        {
            int row = tid >> 2;
            int seg = (tid & 3) * 8;
            int q = q0 + row;
            if (q >= Q) q = Q - 1;    // clamp; garbage rows masked in epilogue
            long g = (brow0 + q) * D + k0 + seg;
            uint32_t soff = (uint32_t)((row * LDSA + seg) * 2);
            cp16(bb + OFF_BHI + soff, q_hi + g);
            cp16(bb + OFF_BLO + soff, q_lo + g);
        }
        asm volatile("cp.async.commit_group;" ::: "memory");
    };

    load_chunk(0);

    for (int cc = 0; cc < nch; ++cc) {
        if (cc + 1 < nch) {
            load_chunk(cc + 1);
            asm volatile("cp.async.wait_group 1;" ::: "memory");
        } else {
            asm volatile("cp.async.wait_group 0;" ::: "memory");
        }
        __syncthreads();

        const uint32_t bb = sbase + (uint32_t)(cc & 1) * BUF_SZ;
        const uint32_t as_hi = bb + OFF_AHI;
        const uint32_t as_lo = bb + OFF_ALO;
        const uint32_t bs_hi = bb + OFF_BHI;
        const uint32_t bs_lo = bb + OFF_BLO;

        #pragma unroll
        for (int kk = 0; kk < KC; kk += 16) {
            uint32_t ah[2][4], al[2][4];
            #pragma unroll
            for (int mi = 0; mi < 2; ++mi) {
                int row = warp_m + mi * 16 + (lane & 15);
                int col = kk + ((lane >> 4) << 3);
                uint32_t addr = (uint32_t)((row * LDSA + col) * 2);
                ldmatrix_x4(ah[mi], as_hi + addr);
                ldmatrix_x4(al[mi], as_lo + addr);
            }
            uint32_t bh[4][2], bl[4][2];
            #pragma unroll
            for (int nb = 0; nb < 2; ++nb) {
                int row = warp_n + nb * 16 + ((lane & 16) >> 1) + (lane & 7);
                int col = kk + ((lane >> 3) & 1) * 8;
                uint32_t addr = (uint32_t)((row * LDSA + col) * 2);
                uint32_t rh[4], rl[4];
                ldmatrix_x4(rh, bs_hi + addr);
                ldmatrix_x4(rl, bs_lo + addr);
                bh[nb * 2 + 0][0] = rh[0]; bh[nb * 2 + 0][1] = rh[1];
                bh[nb * 2 + 1][0] = rh[2]; bh[nb * 2 + 1][1] = rh[3];
                bl[nb * 2 + 0][0] = rl[0]; bl[nb * 2 + 0][1] = rl[1];
                bl[nb * 2 + 1][0] = rl[2]; bl[nb * 2 + 1][1] = rl[3];
            }
            #pragma unroll
            for (int mi = 0; mi < 2; ++mi) {
                #pragma unroll
                for (int ni = 0; ni < 4; ++ni) {
                    mma_bf16(c[mi][ni], ah[mi], bh[ni]);   // hi*hi
                    mma_bf16(c[mi][ni], ah[mi], bl[ni]);   // hi*lo
                    mma_bf16(c[mi][ni], al[mi], bh[ni]);   // lo*hi
                }
            }
        }
        __syncthreads();
    }

    // ---- epilogue: lane-paired float4 vector atomics ----
    const int Wd = width_ptr ? *width_ptr : width_imm;

    #pragma unroll
    for (int mi = 0; mi < 2; ++mi) {
        #pragma unroll
        for (int half = 0; half < 2; ++half) {
            int row = warp_m + mi * 16 + half * 8 + (lane >> 2);
            int f = f0 + row;
            bool ok = (f < F);
            long obase = 0;
            if (ok) {
                long n = arow0 + row;
                int hh = fidx[3 * n + 1];
                int ww = fidx[3 * n + 2];
                obase = (long)b * HWQ + ((long)hh * Wd + ww) * (long)Q;
            }
            #pragma unroll
            for (int ni = 0; ni < 4; ++ni) {
                float v0 = c[mi][ni][half * 2 + 0];
                float v1 = c[mi][ni][half * 2 + 1];
                // partner lane (lane^1) holds the adjacent float2 of this quad
                float p0 = __shfl_xor_sync(0xFFFFFFFFu, v0, 1);
                float p1 = __shfl_xor_sync(0xFFFFFFFFu, v1, 1);
                if (ok && (lane & 1) == 0) {
                    int q = q0 + warp_n + ni * 8 + 2 * (lane & 3); // offsets 0 or 4
                    if (q + 3 < Q) {
                        atomicAdd(reinterpret_cast<float4*>(out + obase + q),
                                  make_float4(v0, v1, p0, p1));
                    } else {
                        if (q     < Q) atomicAdd(out + obase + q,     v0);
                        if (q + 1 < Q) atomicAdd(out + obase + q + 1, v1);
                        if (q + 2 < Q) atomicAdd(out + obase + q + 2, p0);
                        if (q + 3 < Q) atomicAdd(out + obase + q + 3, p1);
                    }
                }
            }
        }
    }
}

// ---------------------------------------------------------------------------
static int isqrt_host(long v) {
    int r = (int)(sqrt((double)v) + 0.5);
    while ((long)r * r > v) --r;
    while ((long)(r + 1) * (r + 1) <= v) ++r;
    return r;
}

extern "C" void kernel_launch(void* const* d_in, const int* in_sizes, int n_in,
                              void* d_out, int out_size) {
    // Input order: queries, feature_values, feature_indices, query_batch_offsets,
    // feature_batch_offsets, height, width, W0,b0, W1,b1, W2,b2, W3,b3.
    const float* queries = (const float*)d_in[0];
    const float* fv      = (const float*)d_in[1];
    const int*   fidx    = (const int*)d_in[2];

    bool scalars_present = (n_in >= 15 && in_sizes[5] == 1 && in_sizes[6] == 1);
    int wbase = scalars_present ? 7 : 5;
    const int* width_ptr = scalars_present ? (const int*)d_in[6] : nullptr;

    const float* Wl[4];
    const float* bl[4];
    for (int i = 0; i < 4; ++i) {
        Wl[i] = (const float*)d_in[wbase + 2 * i];
        bl[i] = (const float*)d_in[wbase + 2 * i + 1];
    }

    const int D  = in_sizes[wbase + 1];       // len(b0)
    const int Mq = in_sizes[0] / D;           // B*Q
    const int B  = in_sizes[3] - 1;
    const int Q  = Mq / B;
    const int NF = in_sizes[1] / D;           // B*F
    const int F  = NF / B;
    const long HWQ = (long)out_size / B;      // H*W*Q
    const int width_imm = isqrt_host(HWQ / Q);

    float *buf0 = nullptr, *buf1 = nullptr;
    __nv_bfloat16 *fv_hi = nullptr, *fv_lo = nullptr, *q_hi = nullptr, *q_lo = nullptr;
    cudaGetSymbolAddress((void**)&buf0, g_mlp_a);
    cudaGetSymbolAddress((void**)&buf1, g_mlp_b);
    cudaGetSymbolAddress((void**)&fv_hi, g_fv_hi);
    cudaGetSymbolAddress((void**)&fv_lo, g_fv_lo);
    cudaGetSymbolAddress((void**)&q_hi, g_q_hi);
    cudaGetSymbolAddress((void**)&q_lo, g_q_lo);

    // One-time setup (no device work; deterministic across calls)
    static cudaStream_t side = nullptr;
    static cudaEvent_t ev_fork = nullptr, ev_join = nullptr;
    static bool attr_done = false;
    if (!side) {
        cudaStreamCreateWithFlags(&side, cudaStreamNonBlocking);
        cudaEventCreateWithFlags(&ev_fork, cudaEventDisableTiming);
        cudaEventCreateWithFlags(&ev_join, cudaEventDisableTiming);
    }
    if (!attr_done) {
        cudaFuncSetAttribute(logits_mma_kernel,
                             cudaFuncAttributeMaxDynamicSharedMemorySize,
                             LOGITS_SMEM);
        attr_done = true;
    }

    // ---- fork: side stream zeroes output and converts fv while the MLP
    //      chain runs on the main stream ----
    cudaEventRecord(ev_fork, 0);
    cudaStreamWaitEvent(side, ev_fork, 0);

    cudaMemsetAsync(d_out, 0, (size_t)out_size * sizeof(float), side);
    {
        long n4 = (long)NF * D / 4;
        convert_split_kernel<<<(int)DIV_UP(n4, 256L), 256, 0, side>>>(fv, fv_hi,
                                                                      fv_lo, n4);
    }

    // main stream: 3x (linear+relu), 1x linear, then convert q
    {
        dim3 grid(DIV_UP(Mq, 32), DIV_UP(D, 32));
        mlp_kernel<1><<<grid, 256>>>(queries, Wl[0], bl[0], buf0, Mq, D, D);
        mlp_kernel<1><<<grid, 256>>>(buf0,    Wl[1], bl[1], buf1, Mq, D, D);
        mlp_kernel<1><<<grid, 256>>>(buf1,    Wl[2], bl[2], buf0, Mq, D, D);
        mlp_kernel<0><<<grid, 256>>>(buf0,    Wl[3], bl[3], buf1, Mq, D, D);
    }
    {
        long n4 = (long)Mq * D / 4;
        convert_split_kernel<<<(int)DIV_UP(n4, 256L), 256>>>(buf1, q_hi, q_lo, n4);
    }

    // ---- join ----
    cudaEventRecord(ev_join, side);
    cudaStreamWaitEvent(0, ev_join, 0);

    // Logits GEMM (pipelined, pure-MMA mainloop) fused with scatter-add
    {
        dim3 grid(DIV_UP(Q, QTILE), DIV_UP(F, FTILE), B);
        logits_mma_kernel<<<grid, 256, LOGITS_SMEM>>>(fv_hi, fv_lo, q_hi, q_lo,
                                                      fidx, (float*)d_out,
                                                      width_ptr, width_imm,
                                                      F, Q, D, HWQ);
    }
}

// round 7
// speedup vs baseline: 1.2319x; 1.0326x over previous
#include <cuda_runtime.h>
#include <cuda_bf16.h>
#include <cstdint>
#include <cmath>

#define DIV_UP(a, b) (((a) + (b) - 1) / (b))

// Scratch (static device allocations — the only legal kind here)
__device__ __align__(16) float g_mlp_a[1 << 20];            // 4 MB
__device__ __align__(16) float g_mlp_b[1 << 20];            // 4 MB
__device__ __align__(16) __nv_bfloat16 g_fv_hi[1 << 24];    // 33.5 MB
__device__ __align__(16) __nv_bfloat16 g_fv_lo[1 << 24];    // 33.5 MB
__device__ __align__(16) __nv_bfloat16 g_q_hi[1 << 19];     // 1 MB
__device__ __align__(16) __nv_bfloat16 g_q_lo[1 << 19];     // 1 MB

// ============================================================================
// helpers
// ============================================================================
__device__ __forceinline__ uint32_t smem_to_u32(const void* smem_ptr) {
    uint32_t addr;
    asm("{ .reg .u64 tmp; cvta.to.shared.u64 tmp, %1; cvt.u32.u64 %0, tmp; }"
        : "=r"(addr) : "l"(smem_ptr));
    return addr;
}

__device__ __forceinline__ void ldmatrix_x4(uint32_t* r, uint32_t addr) {
    asm volatile("ldmatrix.sync.aligned.m8n8.x4.shared.b16 {%0,%1,%2,%3}, [%4];"
                 : "=r"(r[0]), "=r"(r[1]), "=r"(r[2]), "=r"(r[3]) : "r"(addr));
}

// D = A(bf16) * B(bf16)^T + D, m16n8k16
__device__ __forceinline__ void mma_bf16(float* c, const uint32_t* a,
                                         const uint32_t* b) {
    asm volatile(
        "mma.sync.aligned.m16n8k16.row.col.f32.bf16.bf16.f32 "
        "{%0,%1,%2,%3}, {%4,%5,%6,%7}, {%8,%9}, {%0,%1,%2,%3};"
        : "+f"(c[0]), "+f"(c[1]), "+f"(c[2]), "+f"(c[3])
        : "r"(a[0]), "r"(a[1]), "r"(a[2]), "r"(a[3]), "r"(b[0]), "r"(b[1]));
}

__device__ __forceinline__ void cp16(uint32_t smem, const void* g) {
    asm volatile("cp.async.cg.shared.global [%0], [%1], 16;"
                 :: "r"(smem), "l"(g));
}

// split fp32 pair into packed bf16x2 hi and lo planes
__device__ __forceinline__ void split2(float x, float y, uint32_t& hi, uint32_t& lo) {
    __nv_bfloat16 hx = __float2bfloat16(x);
    __nv_bfloat16 hy = __float2bfloat16(y);
    __nv_bfloat16 lx = __float2bfloat16(x - __bfloat162float(hx));
    __nv_bfloat16 ly = __float2bfloat16(y - __bfloat162float(hy));
    hi = (uint32_t)__bfloat16_as_ushort(hx) | ((uint32_t)__bfloat16_as_ushort(hy) << 16);
    lo = (uint32_t)__bfloat16_as_ushort(lx) | ((uint32_t)__bfloat16_as_ushort(ly) << 16);
}

// ============================================================================
// fp32 -> bf16 hi/lo plane conversion (one pass, streaming)
// ============================================================================
__global__ void __launch_bounds__(256)
convert_split_kernel(const float* __restrict__ in,
                     __nv_bfloat16* __restrict__ hi,
                     __nv_bfloat16* __restrict__ lo, long n4) {
    long i = (long)blockIdx.x * blockDim.x + threadIdx.x;
    if (i >= n4) return;
    float4 v = reinterpret_cast<const float4*>(in)[i];
    uint32_t h0, l0, h1, l1;
    split2(v.x, v.y, h0, l0);
    split2(v.z, v.w, h1, l1);
    reinterpret_cast<uint2*>(hi)[i] = make_uint2(h0, h1);
    reinterpret_cast<uint2*>(lo)[i] = make_uint2(l0, l1);
}

// ============================================================================
// MLP layer: Y[M,N] = act(X[M,K] @ W[N,K]^T + bias). 32x32 tiles, BK=32.
// Register-staged double buffering: next chunk's LDG issued before compute.
// SPLIT=1: final layer writes bf16 hi/lo planes directly (no relu).
// ============================================================================
template <int RELU, int SPLIT>
__global__ void __launch_bounds__(256)
mlp_kernel(const float* __restrict__ X, const float* __restrict__ Wm,
           const float* __restrict__ bias, float* __restrict__ Y,
           __nv_bfloat16* __restrict__ Yhi, __nv_bfloat16* __restrict__ Ylo,
           int M, int K, int N) {
    constexpr int BM = 32, BN = 32, BK = 32;
    __shared__ __align__(16) float Xs[BK][BM + 1];
    __shared__ __align__(16) float Ws[BK][BN + 1];

    const int m0 = blockIdx.x * BM;
    const int n0 = blockIdx.y * BN;
    const int tid = threadIdx.x;
    const int ti = tid & 15;
    const int tj = tid >> 4;
    const int lr = tid >> 3;          // load row 0..31
    const int lc = (tid & 7) * 4;     // load col (float4)

    float acc[2][2] = {};
    float4 xr, wr;

    // prologue: stage chunk 0
    xr = (m0 + lr < M)
         ? *reinterpret_cast<const float4*>(X + (long)(m0 + lr) * K + lc)
         : make_float4(0.f, 0.f, 0.f, 0.f);
    wr = *reinterpret_cast<const float4*>(Wm + (long)(n0 + lr) * K + lc);

    for (int k0 = 0; k0 < K; k0 += BK) {
        Xs[lc + 0][lr] = xr.x; Xs[lc + 1][lr] = xr.y;
        Xs[lc + 2][lr] = xr.z; Xs[lc + 3][lr] = xr.w;
        Ws[lc + 0][lr] = wr.x; Ws[lc + 1][lr] = wr.y;
        Ws[lc + 2][lr] = wr.z; Ws[lc + 3][lr] = wr.w;
        __syncthreads();

        if (k0 + BK < K) {   // stage next chunk; latency overlaps compute
            xr = (m0 + lr < M)
                 ? *reinterpret_cast<const float4*>(X + (long)(m0 + lr) * K + k0 + BK + lc)
                 : make_float4(0.f, 0.f, 0.f, 0.f);
            wr = *reinterpret_cast<const float4*>(Wm + (long)(n0 + lr) * K + k0 + BK + lc);
        }

        #pragma unroll
        for (int k = 0; k < BK; ++k) {
            float a0 = Xs[k][ti * 2 + 0];
            float a1 = Xs[k][ti * 2 + 1];
            float b0 = Ws[k][tj * 2 + 0];
            float b1 = Ws[k][tj * 2 + 1];
            acc[0][0] = fmaf(a0, b0, acc[0][0]);
            acc[0][1] = fmaf(a0, b1, acc[0][1]);
            acc[1][0] = fmaf(a1, b0, acc[1][0]);
            acc[1][1] = fmaf(a1, b1, acc[1][1]);
        }
        __syncthreads();
    }

    const int n = n0 + tj * 2;   // even
    const float bb0 = bias[n], bb1 = bias[n + 1];
    #pragma unroll
    for (int s = 0; s < 2; ++s) {
        int m = m0 + ti * 2 + s;
        if (m >= M) continue;
        float v0 = acc[s][0] + bb0;
        float v1 = acc[s][1] + bb1;
        if (SPLIT) {
            uint32_t h, l;
            split2(v0, v1, h, l);
            reinterpret_cast<uint32_t*>(Yhi)[((long)m * N + n) >> 1] = h;
            reinterpret_cast<uint32_t*>(Ylo)[((long)m * N + n) >> 1] = l;
        } else {
            if (RELU) { v0 = fmaxf(v0, 0.f); v1 = fmaxf(v1, 0.f); }
            Y[(long)m * N + n]     = v0;
            Y[(long)m * N + n + 1] = v1;
        }
    }
}

// ============================================================================
// Logits GEMM: preconverted bf16 hi/lo planes, cp.async double-buffered,
// mma.sync mainloop, float4 vector-atomic scatter epilogue.
// CTA tile: 128(f) x 64(q), 8 warps 4x2, warp tile 32x32. 3 CTAs/SM.
// ============================================================================
constexpr int FTILE = 128;
constexpr int QTILE = 64;
constexpr int KC    = 32;
constexpr int LDSA  = KC + 8;   // bf16 elems per smem row (80B stride, 16B-aligned)

constexpr int OFF_AHI = 0;
constexpr int OFF_ALO = OFF_AHI + FTILE * LDSA * 2;   // 10240
constexpr int OFF_BHI = OFF_ALO + FTILE * LDSA * 2;   // 20480
constexpr int OFF_BLO = OFF_BHI + QTILE * LDSA * 2;   // 25600
constexpr int BUF_SZ  = OFF_BLO + QTILE * LDSA * 2;   // 30720
constexpr int LOGITS_SMEM = 2 * BUF_SZ;               // 61440 (x3 CTA = 184KB)

__global__ void __launch_bounds__(256, 3)
logits_mma_kernel(const __nv_bfloat16* __restrict__ fv_hi,   // [B*F, D]
                  const __nv_bfloat16* __restrict__ fv_lo,
                  const __nv_bfloat16* __restrict__ q_hi,    // [B*Q, D]
                  const __nv_bfloat16* __restrict__ q_lo,
                  const int* __restrict__ fidx,              // [B*F, 3]
                  float* __restrict__ out,
                  const int* __restrict__ width_ptr, int width_imm,
                  int F, int Q, int D, long HWQ) {
    extern __shared__ __align__(16) char smem[];
    const uint32_t sbase = smem_to_u32(smem);

    const int tid  = threadIdx.x;
    const int wid  = tid >> 5;
    const int lane = tid & 31;
    const int b  = blockIdx.z;
    const int q0 = blockIdx.x * QTILE;   // q fastest -> A tiles reused in L2
    const int f0 = blockIdx.y * FTILE;

    const int warp_m = (wid & 3) * 32;
    const int warp_n = (wid >> 2) * 32;

    const long arow0 = (long)b * F + f0;
    const long brow0 = (long)b * Q;

    // ---- prefetch scatter indices for this thread's 4 output rows ----
    const int Wd = width_ptr ? *width_ptr : width_imm;
    int hh[4], ww[4];
    #pragma unroll
    for (int mi = 0; mi < 2; ++mi) {
        #pragma unroll
        for (int half = 0; half < 2; ++half) {
            int row = warp_m + mi * 16 + half * 8 + (lane >> 2);
            long n = arow0 + row;
            hh[mi * 2 + half] = fidx[3 * n + 1];
            ww[mi * 2 + half] = fidx[3 * n + 2];
        }
    }

    float c[2][4][4] = {};

    const int nch = D / KC;

    auto load_chunk = [&](int cc) {
        const int k0 = cc * KC;
        const uint32_t bb = sbase + (uint32_t)(cc & 1) * BUF_SZ;
        #pragma unroll
        for (int i = 0; i < 2; ++i) {
            int idx = tid + i * 256;
            int row = idx >> 2;
            int seg = (idx & 3) * 8;
            long g = (arow0 + row) * D + k0 + seg;
            uint32_t soff = (uint32_t)((row * LDSA + seg) * 2);
            cp16(bb + OFF_AHI + soff, fv_hi + g);
            cp16(bb + OFF_ALO + soff, fv_lo + g);
        }
        {
            int row = tid >> 2;
            int seg = (tid & 3) * 8;
            int q = q0 + row;
            if (q >= Q) q = Q - 1;    // clamp; garbage rows masked in epilogue
            long g = (brow0 + q) * D + k0 + seg;
            uint32_t soff = (uint32_t)((row * LDSA + seg) * 2);
            cp16(bb + OFF_BHI + soff, q_hi + g);
            cp16(bb + OFF_BLO + soff, q_lo + g);
        }
        asm volatile("cp.async.commit_group;" ::: "memory");
    };

    load_chunk(0);

    for (int cc = 0; cc < nch; ++cc) {
        if (cc + 1 < nch) {
            load_chunk(cc + 1);
            asm volatile("cp.async.wait_group 1;" ::: "memory");
        } else {
            asm volatile("cp.async.wait_group 0;" ::: "memory");
        }
        __syncthreads();

        const uint32_t bb = sbase + (uint32_t)(cc & 1) * BUF_SZ;
        const uint32_t as_hi = bb + OFF_AHI;
        const uint32_t as_lo = bb + OFF_ALO;
        const uint32_t bs_hi = bb + OFF_BHI;
        const uint32_t bs_lo = bb + OFF_BLO;

        #pragma unroll
        for (int kk = 0; kk < KC; kk += 16) {
            uint32_t ah[2][4], al[2][4];
            #pragma unroll
            for (int mi = 0; mi < 2; ++mi) {
                int row = warp_m + mi * 16 + (lane & 15);
                int col = kk + ((lane >> 4) << 3);
                uint32_t addr = (uint32_t)((row * LDSA + col) * 2);
                ldmatrix_x4(ah[mi], as_hi + addr);
                ldmatrix_x4(al[mi], as_lo + addr);
            }
            uint32_t bh[4][2], bl[4][2];
            #pragma unroll
            for (int nb = 0; nb < 2; ++nb) {
                int row = warp_n + nb * 16 + ((lane & 16) >> 1) + (lane & 7);
                int col = kk + ((lane >> 3) & 1) * 8;
                uint32_t addr = (uint32_t)((row * LDSA + col) * 2);
                uint32_t rh[4], rl[4];
                ldmatrix_x4(rh, bs_hi + addr);
                ldmatrix_x4(rl, bs_lo + addr);
                bh[nb * 2 + 0][0] = rh[0]; bh[nb * 2 + 0][1] = rh[1];
                bh[nb * 2 + 1][0] = rh[2]; bh[nb * 2 + 1][1] = rh[3];
                bl[nb * 2 + 0][0] = rl[0]; bl[nb * 2 + 0][1] = rl[1];
                bl[nb * 2 + 1][0] = rl[2]; bl[nb * 2 + 1][1] = rl[3];
            }
            #pragma unroll
            for (int mi = 0; mi < 2; ++mi) {
                #pragma unroll
                for (int ni = 0; ni < 4; ++ni) {
                    mma_bf16(c[mi][ni], ah[mi], bh[ni]);   // hi*hi
                    mma_bf16(c[mi][ni], ah[mi], bl[ni]);   // hi*lo
                    mma_bf16(c[mi][ni], al[mi], bh[ni]);   // lo*hi
                }
            }
        }
        __syncthreads();
    }

    // ---- epilogue: lane-paired float4 vector atomics ----
    #pragma unroll
    for (int mi = 0; mi < 2; ++mi) {
        #pragma unroll
        for (int half = 0; half < 2; ++half) {
            int row = warp_m + mi * 16 + half * 8 + (lane >> 2);
            int f = f0 + row;
            bool ok = (f < F);
            long obase = (long)b * HWQ +
                         ((long)hh[mi * 2 + half] * Wd + ww[mi * 2 + half]) * (long)Q;
            #pragma unroll
            for (int ni = 0; ni < 4; ++ni) {
                float v0 = c[mi][ni][half * 2 + 0];
                float v1 = c[mi][ni][half * 2 + 1];
                float p0 = __shfl_xor_sync(0xFFFFFFFFu, v0, 1);
                float p1 = __shfl_xor_sync(0xFFFFFFFFu, v1, 1);
                if (ok && (lane & 1) == 0) {
                    int q = q0 + warp_n + ni * 8 + 2 * (lane & 3); // 0 or 4
                    if (q + 3 < Q) {
                        atomicAdd(reinterpret_cast<float4*>(out + obase + q),
                                  make_float4(v0, v1, p0, p1));
                    } else {
                        if (q     < Q) atomicAdd(out + obase + q,     v0);
                        if (q + 1 < Q) atomicAdd(out + obase + q + 1, v1);
                        if (q + 2 < Q) atomicAdd(out + obase + q + 2, p0);
                        if (q + 3 < Q) atomicAdd(out + obase + q + 3, p1);
                    }
                }
            }
        }
    }
}

// ---------------------------------------------------------------------------
static int isqrt_host(long v) {
    int r = (int)(sqrt((double)v) + 0.5);
    while ((long)r * r > v) --r;
    while ((long)(r + 1) * (r + 1) <= v) ++r;
    return r;
}

extern "C" void kernel_launch(void* const* d_in, const int* in_sizes, int n_in,
                              void* d_out, int out_size) {
    // Input order: queries, feature_values, feature_indices, query_batch_offsets,
    // feature_batch_offsets, height, width, W0,b0, W1,b1, W2,b2, W3,b3.
    const float* queries = (const float*)d_in[0];
    const float* fv      = (const float*)d_in[1];
    const int*   fidx    = (const int*)d_in[2];

    bool scalars_present = (n_in >= 15 && in_sizes[5] == 1 && in_sizes[6] == 1);
    int wbase = scalars_present ? 7 : 5;
    const int* width_ptr = scalars_present ? (const int*)d_in[6] : nullptr;

    const float* Wl[4];
    const float* bl[4];
    for (int i = 0; i < 4; ++i) {
        Wl[i] = (const float*)d_in[wbase + 2 * i];
        bl[i] = (const float*)d_in[wbase + 2 * i + 1];
    }

    const int D  = in_sizes[wbase + 1];       // len(b0)
    const int Mq = in_sizes[0] / D;           // B*Q
    const int B  = in_sizes[3] - 1;
    const int Q  = Mq / B;
    const int NF = in_sizes[1] / D;           // B*F
    const int F  = NF / B;
    const long HWQ = (long)out_size / B;      // H*W*Q
    const int width_imm = isqrt_host(HWQ / Q);

    float *buf0 = nullptr, *buf1 = nullptr;
    __nv_bfloat16 *fv_hi = nullptr, *fv_lo = nullptr, *q_hi = nullptr, *q_lo = nullptr;
    cudaGetSymbolAddress((void**)&buf0, g_mlp_a);
    cudaGetSymbolAddress((void**)&buf1, g_mlp_b);
    cudaGetSymbolAddress((void**)&fv_hi, g_fv_hi);
    cudaGetSymbolAddress((void**)&fv_lo, g_fv_lo);
    cudaGetSymbolAddress((void**)&q_hi, g_q_hi);
    cudaGetSymbolAddress((void**)&q_lo, g_q_lo);

    // One-time setup (no device work; deterministic across calls)
    static cudaStream_t side1 = nullptr, side2 = nullptr;
    static cudaEvent_t ev_fork = nullptr, ev_j1 = nullptr, ev_j2 = nullptr;
    static bool attr_done = false;
    if (!side1) {
        cudaStreamCreateWithFlags(&side1, cudaStreamNonBlocking);
        cudaStreamCreateWithFlags(&side2, cudaStreamNonBlocking);
        cudaEventCreateWithFlags(&ev_fork, cudaEventDisableTiming);
        cudaEventCreateWithFlags(&ev_j1, cudaEventDisableTiming);
        cudaEventCreateWithFlags(&ev_j2, cudaEventDisableTiming);
    }
    if (!attr_done) {
        cudaFuncSetAttribute(logits_mma_kernel,
                             cudaFuncAttributeMaxDynamicSharedMemorySize,
                             LOGITS_SMEM);
        attr_done = true;
    }

    // ---- fork: side1 converts fv; side2 zeroes output; main runs the MLP ----
    cudaEventRecord(ev_fork, 0);
    cudaStreamWaitEvent(side1, ev_fork, 0);
    cudaStreamWaitEvent(side2, ev_fork, 0);

    {
        long n4 = (long)NF * D / 4;
        convert_split_kernel<<<(int)DIV_UP(n4, 256L), 256, 0, side1>>>(fv, fv_hi,
                                                                       fv_lo, n4);
    }
    cudaMemsetAsync(d_out, 0, (size_t)out_size * sizeof(float), side2);

    // main stream: 3x (linear+relu), final layer fused with bf16 split
    {
        dim3 grid(DIV_UP(Mq, 32), DIV_UP(D, 32));
        mlp_kernel<1, 0><<<grid, 256>>>(queries, Wl[0], bl[0], buf0,
                                        nullptr, nullptr, Mq, D, D);
        mlp_kernel<1, 0><<<grid, 256>>>(buf0, Wl[1], bl[1], buf1,
                                        nullptr, nullptr, Mq, D, D);
        mlp_kernel<1, 0><<<grid, 256>>>(buf1, Wl[2], bl[2], buf0,
                                        nullptr, nullptr, Mq, D, D);
        mlp_kernel<0, 1><<<grid, 256>>>(buf0, Wl[3], bl[3], nullptr,
                                        q_hi, q_lo, Mq, D, D);
    }

    // ---- join ----
    cudaEventRecord(ev_j1, side1);
    cudaEventRecord(ev_j2, side2);
    cudaStreamWaitEvent(0, ev_j1, 0);
    cudaStreamWaitEvent(0, ev_j2, 0);

    // Logits GEMM (pipelined, pure-MMA mainloop) fused with scatter-add
    {
        dim3 grid(DIV_UP(Q, QTILE), DIV_UP(F, FTILE), B);
        logits_mma_kernel<<<grid, 256, LOGITS_SMEM>>>(fv_hi, fv_lo, q_hi, q_lo,
                                                      fidx, (float*)d_out,
                                                      width_ptr, width_imm,
                                                      F, Q, D, HWQ);
    }
}

// round 8
// speedup vs baseline: 1.3158x; 1.0681x over previous
#include <cuda_runtime.h>
#include <cuda_bf16.h>
#include <cstdint>
#include <cmath>

#define DIV_UP(a, b) (((a) + (b) - 1) / (b))

// Scratch (static device allocations — the only legal kind here)
__device__ __align__(16) float g_mlp_a[1 << 20];     // 4 MB
__device__ __align__(16) float g_mlp_b[1 << 20];     // 4 MB
__device__ __align__(16) float g_fv_t[1 << 24];      // 67 MB, tf32-rounded fv
__device__ __align__(16) float g_q_t[1 << 19];       // 2 MB, tf32-rounded q

// ============================================================================
// helpers
// ============================================================================
__device__ __forceinline__ uint32_t smem_to_u32(const void* smem_ptr) {
    uint32_t addr;
    asm("{ .reg .u64 tmp; cvta.to.shared.u64 tmp, %1; cvt.u32.u64 %0, tmp; }"
        : "=r"(addr) : "l"(smem_ptr));
    return addr;
}

// round fp32 -> tf32 (round to nearest; result is fp32 with low mantissa zero)
__device__ __forceinline__ float to_tf32(float x) {
    uint32_t r;
    asm("cvt.rna.tf32.f32 %0, %1;" : "=r"(r) : "f"(x));
    return __uint_as_float(r);
}

// D += A(tf32) * B(tf32)^T, m16n8k8
__device__ __forceinline__ void mma_tf32(float* c, const uint32_t* a,
                                         const uint32_t* b) {
    asm volatile(
        "mma.sync.aligned.m16n8k8.row.col.f32.tf32.tf32.f32 "
        "{%0,%1,%2,%3}, {%4,%5,%6,%7}, {%8,%9}, {%0,%1,%2,%3};"
        : "+f"(c[0]), "+f"(c[1]), "+f"(c[2]), "+f"(c[3])
        : "r"(a[0]), "r"(a[1]), "r"(a[2]), "r"(a[3]), "r"(b[0]), "r"(b[1]));
}

__device__ __forceinline__ void cp16(uint32_t smem, const void* g) {
    asm volatile("cp.async.cg.shared.global [%0], [%1], 16;"
                 :: "r"(smem), "l"(g));
}

__device__ __forceinline__ uint32_t lds32(uint32_t addr) {
    uint32_t v;
    asm volatile("ld.shared.b32 %0, [%1];" : "=r"(v) : "r"(addr));
    return v;
}

// ============================================================================
// fp32 -> tf32-rounded fp32 (one streaming pass)
// ============================================================================
__global__ void __launch_bounds__(256)
convert_tf32_kernel(const float* __restrict__ in, float* __restrict__ outp,
                    long n4) {
    long i = (long)blockIdx.x * blockDim.x + threadIdx.x;
    if (i >= n4) return;
    float4 v = reinterpret_cast<const float4*>(in)[i];
    v.x = to_tf32(v.x); v.y = to_tf32(v.y);
    v.z = to_tf32(v.z); v.w = to_tf32(v.w);
    reinterpret_cast<float4*>(outp)[i] = v;
}

// ============================================================================
// MLP layer: Y[M,N] = act(X[M,K] @ W[N,K]^T + bias). 32x32 tiles, BK=32.
// SPLIT=1: final layer writes tf32-rounded fp32 directly (no relu).
// ============================================================================
template <int RELU, int SPLIT>
__global__ void __launch_bounds__(256)
mlp_kernel(const float* __restrict__ X, const float* __restrict__ Wm,
           const float* __restrict__ bias, float* __restrict__ Y,
           int M, int K, int N) {
    constexpr int BM = 32, BN = 32, BK = 32;
    __shared__ __align__(16) float Xs[BK][BM + 1];
    __shared__ __align__(16) float Ws[BK][BN + 1];

    const int m0 = blockIdx.x * BM;
    const int n0 = blockIdx.y * BN;
    const int tid = threadIdx.x;
    const int ti = tid & 15;
    const int tj = tid >> 4;
    const int lr = tid >> 3;
    const int lc = (tid & 7) * 4;

    float acc[2][2] = {};
    float4 xr, wr;

    xr = (m0 + lr < M)
         ? *reinterpret_cast<const float4*>(X + (long)(m0 + lr) * K + lc)
         : make_float4(0.f, 0.f, 0.f, 0.f);
    wr = *reinterpret_cast<const float4*>(Wm + (long)(n0 + lr) * K + lc);

    for (int k0 = 0; k0 < K; k0 += BK) {
        Xs[lc + 0][lr] = xr.x; Xs[lc + 1][lr] = xr.y;
        Xs[lc + 2][lr] = xr.z; Xs[lc + 3][lr] = xr.w;
        Ws[lc + 0][lr] = wr.x; Ws[lc + 1][lr] = wr.y;
        Ws[lc + 2][lr] = wr.z; Ws[lc + 3][lr] = wr.w;
        __syncthreads();

        if (k0 + BK < K) {
            xr = (m0 + lr < M)
                 ? *reinterpret_cast<const float4*>(X + (long)(m0 + lr) * K + k0 + BK + lc)
                 : make_float4(0.f, 0.f, 0.f, 0.f);
            wr = *reinterpret_cast<const float4*>(Wm + (long)(n0 + lr) * K + k0 + BK + lc);
        }

        #pragma unroll
        for (int k = 0; k < BK; ++k) {
            float a0 = Xs[k][ti * 2 + 0];
            float a1 = Xs[k][ti * 2 + 1];
            float b0 = Ws[k][tj * 2 + 0];
            float b1 = Ws[k][tj * 2 + 1];
            acc[0][0] = fmaf(a0, b0, acc[0][0]);
            acc[0][1] = fmaf(a0, b1, acc[0][1]);
            acc[1][0] = fmaf(a1, b0, acc[1][0]);
            acc[1][1] = fmaf(a1, b1, acc[1][1]);
        }
        __syncthreads();
    }

    const int n = n0 + tj * 2;
    const float bb0 = bias[n], bb1 = bias[n + 1];
    #pragma unroll
    for (int s = 0; s < 2; ++s) {
        int m = m0 + ti * 2 + s;
        if (m >= M) continue;
        float v0 = acc[s][0] + bb0;
        float v1 = acc[s][1] + bb1;
        if (SPLIT) {
            Y[(long)m * N + n]     = to_tf32(v0);
            Y[(long)m * N + n + 1] = to_tf32(v1);
        } else {
            if (RELU) { v0 = fmaxf(v0, 0.f); v1 = fmaxf(v1, 0.f); }
            Y[(long)m * N + n]     = v0;
            Y[(long)m * N + n + 1] = v1;
        }
    }
}

// ============================================================================
// Logits GEMM: single-pass TF32 mma.sync (3x fewer MACs than bf16 3-term),
// cp.async double-buffered, float4 vector-atomic scatter epilogue.
// CTA tile: 128(f) x 64(q), 8 warps 4x2, warp tile 32x32. 3 CTAs/SM.
// ============================================================================
constexpr int FTILE = 128;
constexpr int QTILE = 64;
constexpr int KC    = 32;
constexpr int LDSA  = KC + 4;   // fp32 elems per smem row (36 -> conflict-free)

constexpr int OFF_A = 0;
constexpr int OFF_B = OFF_A + FTILE * LDSA * 4;       // 18432
constexpr int BUF_SZ = OFF_B + QTILE * LDSA * 4;      // 27648
constexpr int LOGITS_SMEM = 2 * BUF_SZ;               // 55296 (x3 CTA = 166KB)

__global__ void __launch_bounds__(256, 3)
logits_mma_kernel(const float* __restrict__ fv_t,   // [B*F, D] tf32-rounded
                  const float* __restrict__ q_t,    // [B*Q, D] tf32-rounded
                  const int* __restrict__ fidx,     // [B*F, 3]
                  float* __restrict__ out,
                  const int* __restrict__ width_ptr, int width_imm,
                  int F, int Q, int D, long HWQ) {
    extern __shared__ __align__(16) char smem[];
    const uint32_t sbase = smem_to_u32(smem);

    const int tid  = threadIdx.x;
    const int wid  = tid >> 5;
    const int lane = tid & 31;
    const int g    = lane >> 2;    // group id 0..7
    const int tig  = lane & 3;     // thread in group
    const int b  = blockIdx.z;
    const int q0 = blockIdx.x * QTILE;   // q fastest -> A tiles reused in L2
    const int f0 = blockIdx.y * FTILE;

    const int warp_m = (wid & 3) * 32;
    const int warp_n = (wid >> 2) * 32;

    const long arow0 = (long)b * F + f0;
    const long brow0 = (long)b * Q;

    // ---- prefetch scatter indices for this thread's 4 output rows ----
    const int Wd = width_ptr ? *width_ptr : width_imm;
    int hh[4], ww[4];
    #pragma unroll
    for (int mi = 0; mi < 2; ++mi) {
        #pragma unroll
        for (int half = 0; half < 2; ++half) {
            int row = warp_m + mi * 16 + half * 8 + (lane >> 2);
            long n = arow0 + row;
            hh[mi * 2 + half] = fidx[3 * n + 1];
            ww[mi * 2 + half] = fidx[3 * n + 2];
        }
    }

    float c[2][4][4] = {};

    const int nch = D / KC;

    auto load_chunk = [&](int cc) {
        const int k0 = cc * KC;
        const uint32_t bb = sbase + (uint32_t)(cc & 1) * BUF_SZ;
        // A: 128 rows x 32 fp32 = 1024 x 16B
        #pragma unroll
        for (int i = 0; i < 4; ++i) {
            int idx = tid + i * 256;
            int row = idx >> 3;           // 0..127
            int seg = (idx & 7) * 4;      // fp32 col 0,4,..28
            long gg = (arow0 + row) * D + k0 + seg;
            uint32_t soff = (uint32_t)((row * LDSA + seg) * 4);
            cp16(bb + OFF_A + soff, fv_t + gg);
        }
        // B: 64 rows x 32 fp32 = 512 x 16B
        #pragma unroll
        for (int i = 0; i < 2; ++i) {
            int idx = tid + i * 256;
            int row = idx >> 3;           // 0..63
            int seg = (idx & 7) * 4;
            int q = q0 + row;
            if (q >= Q) q = Q - 1;        // clamp; masked in epilogue
            long gg = (brow0 + q) * D + k0 + seg;
            uint32_t soff = (uint32_t)((row * LDSA + seg) * 4);
            cp16(bb + OFF_B + soff, q_t + gg);
        }
        asm volatile("cp.async.commit_group;" ::: "memory");
    };

    load_chunk(0);

    for (int cc = 0; cc < nch; ++cc) {
        if (cc + 1 < nch) {
            load_chunk(cc + 1);
            asm volatile("cp.async.wait_group 1;" ::: "memory");
        } else {
            asm volatile("cp.async.wait_group 0;" ::: "memory");
        }
        __syncthreads();

        const uint32_t bb = sbase + (uint32_t)(cc & 1) * BUF_SZ;
        // per-thread fragment base addresses (byte offsets)
        const uint32_t a_base = bb + OFF_A + (uint32_t)(((warp_m + g) * LDSA + tig) * 4);
        const uint32_t b_base = bb + OFF_B + (uint32_t)(((warp_n + g) * LDSA + tig) * 4);

        #pragma unroll
        for (int kk = 0; kk < KC; kk += 8) {
            uint32_t a[2][4];
            #pragma unroll
            for (int mi = 0; mi < 2; ++mi) {
                uint32_t ad = a_base + (uint32_t)(mi * 16 * LDSA * 4 + kk * 4);
                a[mi][0] = lds32(ad);
                a[mi][1] = lds32(ad + 8 * LDSA * 4);
                a[mi][2] = lds32(ad + 16);
                a[mi][3] = lds32(ad + 8 * LDSA * 4 + 16);
            }
            #pragma unroll
            for (int ni = 0; ni < 4; ++ni) {
                uint32_t bd = b_base + (uint32_t)(ni * 8 * LDSA * 4 + kk * 4);
                uint32_t bf[2];
                bf[0] = lds32(bd);
                bf[1] = lds32(bd + 16);
                mma_tf32(c[0][ni], a[0], bf);
                mma_tf32(c[1][ni], a[1], bf);
            }
        }
        __syncthreads();
    }

    // ---- epilogue: lane-paired float4 vector atomics ----
    #pragma unroll
    for (int mi = 0; mi < 2; ++mi) {
        #pragma unroll
        for (int half = 0; half < 2; ++half) {
            int row = warp_m + mi * 16 + half * 8 + (lane >> 2);
            int f = f0 + row;
            bool ok = (f < F);
            long obase = (long)b * HWQ +
                         ((long)hh[mi * 2 + half] * Wd + ww[mi * 2 + half]) * (long)Q;
            #pragma unroll
            for (int ni = 0; ni < 4; ++ni) {
                float v0 = c[mi][ni][half * 2 + 0];
                float v1 = c[mi][ni][half * 2 + 1];
                float p0 = __shfl_xor_sync(0xFFFFFFFFu, v0, 1);
                float p1 = __shfl_xor_sync(0xFFFFFFFFu, v1, 1);
                if (ok && (lane & 1) == 0) {
                    int q = q0 + warp_n + ni * 8 + 2 * (lane & 3); // 0 or 4
                    if (q + 3 < Q) {
                        atomicAdd(reinterpret_cast<float4*>(out + obase + q),
                                  make_float4(v0, v1, p0, p1));
                    } else {
                        if (q     < Q) atomicAdd(out + obase + q,     v0);
                        if (q + 1 < Q) atomicAdd(out + obase + q + 1, v1);
                        if (q + 2 < Q) atomicAdd(out + obase + q + 2, p0);
                        if (q + 3 < Q) atomicAdd(out + obase + q + 3, p1);
                    }
                }
            }
        }
    }
}

// ---------------------------------------------------------------------------
static int isqrt_host(long v) {
    int r = (int)(sqrt((double)v) + 0.5);
    while ((long)r * r > v) --r;
    while ((long)(r + 1) * (r + 1) <= v) ++r;
    return r;
}

extern "C" void kernel_launch(void* const* d_in, const int* in_sizes, int n_in,
                              void* d_out, int out_size) {
    // Input order: queries, feature_values, feature_indices, query_batch_offsets,
    // feature_batch_offsets, height, width, W0,b0, W1,b1, W2,b2, W3,b3.
    const float* queries = (const float*)d_in[0];
    const float* fv      = (const float*)d_in[1];
    const int*   fidx    = (const int*)d_in[2];

    bool scalars_present = (n_in >= 15 && in_sizes[5] == 1 && in_sizes[6] == 1);
    int wbase = scalars_present ? 7 : 5;
    const int* width_ptr = scalars_present ? (const int*)d_in[6] : nullptr;

    const float* Wl[4];
    const float* bl[4];
    for (int i = 0; i < 4; ++i) {
        Wl[i] = (const float*)d_in[wbase + 2 * i];
        bl[i] = (const float*)d_in[wbase + 2 * i + 1];
    }

    const int D  = in_sizes[wbase + 1];       // len(b0)
    const int Mq = in_sizes[0] / D;           // B*Q
    const int B  = in_sizes[3] - 1;
    const int Q  = Mq / B;
    const int NF = in_sizes[1] / D;           // B*F
    const int F  = NF / B;
    const long HWQ = (long)out_size / B;      // H*W*Q
    const int width_imm = isqrt_host(HWQ / Q);

    float *buf0 = nullptr, *buf1 = nullptr, *fv_t = nullptr, *q_t = nullptr;
    cudaGetSymbolAddress((void**)&buf0, g_mlp_a);
    cudaGetSymbolAddress((void**)&buf1, g_mlp_b);
    cudaGetSymbolAddress((void**)&fv_t, g_fv_t);
    cudaGetSymbolAddress((void**)&q_t, g_q_t);

    // One-time setup (no device work; deterministic across calls)
    static cudaStream_t side1 = nullptr, side2 = nullptr;
    static cudaEvent_t ev_fork = nullptr, ev_j1 = nullptr, ev_j2 = nullptr;
    static bool attr_done = false;
    if (!side1) {
        cudaStreamCreateWithFlags(&side1, cudaStreamNonBlocking);
        cudaStreamCreateWithFlags(&side2, cudaStreamNonBlocking);
        cudaEventCreateWithFlags(&ev_fork, cudaEventDisableTiming);
        cudaEventCreateWithFlags(&ev_j1, cudaEventDisableTiming);
        cudaEventCreateWithFlags(&ev_j2, cudaEventDisableTiming);
    }
    if (!attr_done) {
        cudaFuncSetAttribute(logits_mma_kernel,
                             cudaFuncAttributeMaxDynamicSharedMemorySize,
                             LOGITS_SMEM);
        attr_done = true;
    }

    // ---- fork: side1 tf32-rounds fv; side2 zeroes output; main runs MLP ----
    cudaEventRecord(ev_fork, 0);
    cudaStreamWaitEvent(side1, ev_fork, 0);
    cudaStreamWaitEvent(side2, ev_fork, 0);

    {
        long n4 = (long)NF * D / 4;
        convert_tf32_kernel<<<(int)DIV_UP(n4, 256L), 256, 0, side1>>>(fv, fv_t, n4);
    }
    cudaMemsetAsync(d_out, 0, (size_t)out_size * sizeof(float), side2);

    // main stream: 3x (linear+relu), final layer fused with tf32 rounding
    {
        dim3 grid(DIV_UP(Mq, 32), DIV_UP(D, 32));
        mlp_kernel<1, 0><<<grid, 256>>>(queries, Wl[0], bl[0], buf0, Mq, D, D);
        mlp_kernel<1, 0><<<grid, 256>>>(buf0, Wl[1], bl[1], buf1, Mq, D, D);
        mlp_kernel<1, 0><<<grid, 256>>>(buf1, Wl[2], bl[2], buf0, Mq, D, D);
        mlp_kernel<0, 1><<<grid, 256>>>(buf0, Wl[3], bl[3], q_t, Mq, D, D);
    }

    // ---- join ----
    cudaEventRecord(ev_j1, side1);
    cudaEventRecord(ev_j2, side2);
    cudaStreamWaitEvent(0, ev_j1, 0);
    cudaStreamWaitEvent(0, ev_j2, 0);

    // Logits GEMM (single-pass TF32) fused with scatter-add
    {
        dim3 grid(DIV_UP(Q, QTILE), DIV_UP(F, FTILE), B);
        logits_mma_kernel<<<grid, 256, LOGITS_SMEM>>>(fv_t, q_t, fidx,
                                                      (float*)d_out,
                                                      width_ptr, width_imm,
                                                      F, Q, D, HWQ);
    }
}

// round 9
// speedup vs baseline: 1.6052x; 1.2199x over previous
#include <cuda_runtime.h>
#include <cuda_bf16.h>
#include <cuda_fp16.h>
#include <cstdint>
#include <cmath>

#define DIV_UP(a, b) (((a) + (b) - 1) / (b))

// Scratch (static device allocations — the only legal kind here)
__device__ __align__(16) float g_mlp_a[1 << 20];     // 4 MB
__device__ __align__(16) float g_mlp_b[1 << 20];     // 4 MB
__device__ __align__(16) __half g_fv_h[1 << 24];     // 33.5 MB, fp16 fv
__device__ __align__(16) __half g_q_h[1 << 19];      // 1 MB, fp16 q

// ============================================================================
// helpers
// ============================================================================
__device__ __forceinline__ uint32_t smem_to_u32(const void* smem_ptr) {
    uint32_t addr;
    asm("{ .reg .u64 tmp; cvta.to.shared.u64 tmp, %1; cvt.u32.u64 %0, tmp; }"
        : "=r"(addr) : "l"(smem_ptr));
    return addr;
}

__device__ __forceinline__ void ldmatrix_x4(uint32_t* r, uint32_t addr) {
    asm volatile("ldmatrix.sync.aligned.m8n8.x4.shared.b16 {%0,%1,%2,%3}, [%4];"
                 : "=r"(r[0]), "=r"(r[1]), "=r"(r[2]), "=r"(r[3]) : "r"(addr));
}

// D += A(f16) * B(f16)^T, m16n8k16, fp32 accumulate
__device__ __forceinline__ void mma_f16(float* c, const uint32_t* a,
                                        const uint32_t* b) {
    asm volatile(
        "mma.sync.aligned.m16n8k16.row.col.f32.f16.f16.f32 "
        "{%0,%1,%2,%3}, {%4,%5,%6,%7}, {%8,%9}, {%0,%1,%2,%3};"
        : "+f"(c[0]), "+f"(c[1]), "+f"(c[2]), "+f"(c[3])
        : "r"(a[0]), "r"(a[1]), "r"(a[2]), "r"(a[3]), "r"(b[0]), "r"(b[1]));
}

__device__ __forceinline__ void cp16(uint32_t smem, const void* g) {
    asm volatile("cp.async.cg.shared.global [%0], [%1], 16;"
                 :: "r"(smem), "l"(g));
}

// ============================================================================
// fp32 -> fp16 (one streaming pass, round-to-nearest)
// ============================================================================
__global__ void __launch_bounds__(256)
convert_half_kernel(const float* __restrict__ in, __half* __restrict__ outp,
                    long n4) {
    long i = (long)blockIdx.x * blockDim.x + threadIdx.x;
    if (i >= n4) return;
    float4 v = reinterpret_cast<const float4*>(in)[i];
    __half2 h0 = __floats2half2_rn(v.x, v.y);
    __half2 h1 = __floats2half2_rn(v.z, v.w);
    reinterpret_cast<__half2*>(outp)[2 * i + 0] = h0;
    reinterpret_cast<__half2*>(outp)[2 * i + 1] = h1;
}

// ============================================================================
// MLP layer: Y[M,N] = act(X[M,K] @ W[N,K]^T + bias).
// 16x32 tiles, 128 threads -> 600 CTAs (grid-limited occupancy fix).
// SPLIT=1: final layer writes fp16 directly (no relu).
// ============================================================================
template <int RELU, int SPLIT>
__global__ void __launch_bounds__(128)
mlp_kernel(const float* __restrict__ X, const float* __restrict__ Wm,
           const float* __restrict__ bias, float* __restrict__ Y,
           __half* __restrict__ Yh, int M, int K, int N) {
    constexpr int BM = 16, BN = 32, BK = 32;
    __shared__ __align__(16) float Xs[BK][BM + 1];
    __shared__ __align__(16) float Ws[BK][BN + 1];

    const int m0 = blockIdx.x * BM;
    const int n0 = blockIdx.y * BN;
    const int tid = threadIdx.x;
    const int ti = tid & 7;     // 8 groups x 2 rows = 16
    const int tj = tid >> 3;    // 16 groups x 2 cols = 32
    const int lr = tid >> 3;    // X load row 0..15
    const int lc = (tid & 7) * 4;

    float acc[2][2] = {};
    float4 xr, wr0, wr1;

    // prologue: stage chunk 0
    xr = (m0 + lr < M)
         ? *reinterpret_cast<const float4*>(X + (long)(m0 + lr) * K + lc)
         : make_float4(0.f, 0.f, 0.f, 0.f);
    wr0 = *reinterpret_cast<const float4*>(Wm + (long)(n0 + lr) * K + lc);
    wr1 = *reinterpret_cast<const float4*>(Wm + (long)(n0 + 16 + lr) * K + lc);

    for (int k0 = 0; k0 < K; k0 += BK) {
        Xs[lc + 0][lr] = xr.x; Xs[lc + 1][lr] = xr.y;
        Xs[lc + 2][lr] = xr.z; Xs[lc + 3][lr] = xr.w;
        Ws[lc + 0][lr] = wr0.x; Ws[lc + 1][lr] = wr0.y;
        Ws[lc + 2][lr] = wr0.z; Ws[lc + 3][lr] = wr0.w;
        Ws[lc + 0][16 + lr] = wr1.x; Ws[lc + 1][16 + lr] = wr1.y;
        Ws[lc + 2][16 + lr] = wr1.z; Ws[lc + 3][16 + lr] = wr1.w;
        __syncthreads();

        if (k0 + BK < K) {   // stage next chunk; latency overlaps compute
            xr = (m0 + lr < M)
                 ? *reinterpret_cast<const float4*>(X + (long)(m0 + lr) * K + k0 + BK + lc)
                 : make_float4(0.f, 0.f, 0.f, 0.f);
            wr0 = *reinterpret_cast<const float4*>(Wm + (long)(n0 + lr) * K + k0 + BK + lc);
            wr1 = *reinterpret_cast<const float4*>(Wm + (long)(n0 + 16 + lr) * K + k0 + BK + lc);
        }

        #pragma unroll
        for (int k = 0; k < BK; ++k) {
            float a0 = Xs[k][ti * 2 + 0];
            float a1 = Xs[k][ti * 2 + 1];
            float b0 = Ws[k][tj * 2 + 0];
            float b1 = Ws[k][tj * 2 + 1];
            acc[0][0] = fmaf(a0, b0, acc[0][0]);
            acc[0][1] = fmaf(a0, b1, acc[0][1]);
            acc[1][0] = fmaf(a1, b0, acc[1][0]);
            acc[1][1] = fmaf(a1, b1, acc[1][1]);
        }
        __syncthreads();
    }

    const int n = n0 + tj * 2;
    const float bb0 = bias[n], bb1 = bias[n + 1];
    #pragma unroll
    for (int s = 0; s < 2; ++s) {
        int m = m0 + ti * 2 + s;
        if (m >= M) continue;
        float v0 = acc[s][0] + bb0;
        float v1 = acc[s][1] + bb1;
        if (SPLIT) {
            *reinterpret_cast<__half2*>(Yh + (long)m * N + n) =
                __floats2half2_rn(v0, v1);
        } else {
            if (RELU) { v0 = fmaxf(v0, 0.f); v1 = fmaxf(v1, 0.f); }
            Y[(long)m * N + n]     = v0;
            Y[(long)m * N + n + 1] = v1;
        }
    }
}

// ============================================================================
// Logits GEMM: single-pass fp16 m16n8k16 (HALF the HMMA instructions of R8),
// cp.async double-buffered, float4 vector-atomic scatter epilogue.
// CTA tile: 128(f) x 64(q), 8 warps 4x2, warp tile 32x32. 3 CTAs/SM.
// ============================================================================
constexpr int FTILE = 128;
constexpr int QTILE = 64;
constexpr int KC    = 32;
constexpr int LDSA  = KC + 8;   // fp16 elems per smem row (80B stride)

constexpr int OFF_A = 0;
constexpr int OFF_B = OFF_A + FTILE * LDSA * 2;       // 10240
constexpr int BUF_SZ = OFF_B + QTILE * LDSA * 2;      // 15360
constexpr int LOGITS_SMEM = 2 * BUF_SZ;               // 30720

__global__ void __launch_bounds__(256, 3)
logits_mma_kernel(const __half* __restrict__ fv_h,   // [B*F, D] fp16
                  const __half* __restrict__ q_h,    // [B*Q, D] fp16
                  const int* __restrict__ fidx,      // [B*F, 3]
                  float* __restrict__ out,
                  const int* __restrict__ width_ptr, int width_imm,
                  int F, int Q, int D, long HWQ) {
    extern __shared__ __align__(16) char smem[];
    const uint32_t sbase = smem_to_u32(smem);

    const int tid  = threadIdx.x;
    const int wid  = tid >> 5;
    const int lane = tid & 31;
    const int b  = blockIdx.z;
    const int q0 = blockIdx.x * QTILE;   // q fastest -> A tiles reused in L2
    const int f0 = blockIdx.y * FTILE;

    const int warp_m = (wid & 3) * 32;
    const int warp_n = (wid >> 2) * 32;

    const long arow0 = (long)b * F + f0;
    const long brow0 = (long)b * Q;

    // ---- prefetch scatter indices for this thread's 4 output rows ----
    const int Wd = width_ptr ? *width_ptr : width_imm;
    int hh[4], ww[4];
    #pragma unroll
    for (int mi = 0; mi < 2; ++mi) {
        #pragma unroll
        for (int half = 0; half < 2; ++half) {
            int row = warp_m + mi * 16 + half * 8 + (lane >> 2);
            long n = arow0 + row;
            hh[mi * 2 + half] = fidx[3 * n + 1];
            ww[mi * 2 + half] = fidx[3 * n + 2];
        }
    }

    float c[2][4][4] = {};

    const int nch = D / KC;

    auto load_chunk = [&](int cc) {
        const int k0 = cc * KC;
        const uint32_t bb = sbase + (uint32_t)(cc & 1) * BUF_SZ;
        // A: 128 rows x 32 fp16 = 512 x 16B
        #pragma unroll
        for (int i = 0; i < 2; ++i) {
            int idx = tid + i * 256;
            int row = idx >> 2;           // 0..127
            int seg = (idx & 3) * 8;      // fp16 col 0,8,16,24
            long gg = (arow0 + row) * D + k0 + seg;
            uint32_t soff = (uint32_t)((row * LDSA + seg) * 2);
            cp16(bb + OFF_A + soff, fv_h + gg);
        }
        // B: 64 rows x 32 fp16 = 256 x 16B
        {
            int row = tid >> 2;           // 0..63
            int seg = (tid & 3) * 8;
            int q = q0 + row;
            if (q >= Q) q = Q - 1;        // clamp; masked in epilogue
            long gg = (brow0 + q) * D + k0 + seg;
            uint32_t soff = (uint32_t)((row * LDSA + seg) * 2);
            cp16(bb + OFF_B + soff, q_h + gg);
        }
        asm volatile("cp.async.commit_group;" ::: "memory");
    };

    load_chunk(0);

    for (int cc = 0; cc < nch; ++cc) {
        if (cc + 1 < nch) {
            load_chunk(cc + 1);
            asm volatile("cp.async.wait_group 1;" ::: "memory");
        } else {
            asm volatile("cp.async.wait_group 0;" ::: "memory");
        }
        __syncthreads();

        const uint32_t bb = sbase + (uint32_t)(cc & 1) * BUF_SZ;
        const uint32_t as = bb + OFF_A;
        const uint32_t bs = bb + OFF_B;

        #pragma unroll
        for (int kk = 0; kk < KC; kk += 16) {
            uint32_t a[2][4];
            #pragma unroll
            for (int mi = 0; mi < 2; ++mi) {
                int row = warp_m + mi * 16 + (lane & 15);
                int col = kk + ((lane >> 4) << 3);
                uint32_t addr = (uint32_t)((row * LDSA + col) * 2);
                ldmatrix_x4(a[mi], as + addr);
            }
            uint32_t bfr[4][2];
            #pragma unroll
            for (int nb = 0; nb < 2; ++nb) {
                int row = warp_n + nb * 16 + ((lane & 16) >> 1) + (lane & 7);
                int col = kk + ((lane >> 3) & 1) * 8;
                uint32_t addr = (uint32_t)((row * LDSA + col) * 2);
                uint32_t r[4];
                ldmatrix_x4(r, bs + addr);
                bfr[nb * 2 + 0][0] = r[0]; bfr[nb * 2 + 0][1] = r[1];
                bfr[nb * 2 + 1][0] = r[2]; bfr[nb * 2 + 1][1] = r[3];
            }
            #pragma unroll
            for (int mi = 0; mi < 2; ++mi) {
                #pragma unroll
                for (int ni = 0; ni < 4; ++ni) {
                    mma_f16(c[mi][ni], a[mi], bfr[ni]);
                }
            }
        }
        __syncthreads();
    }

    // ---- epilogue: lane-paired float4 vector atomics ----
    #pragma unroll
    for (int mi = 0; mi < 2; ++mi) {
        #pragma unroll
        for (int half = 0; half < 2; ++half) {
            int row = warp_m + mi * 16 + half * 8 + (lane >> 2);
            int f = f0 + row;
            bool ok = (f < F);
            long obase = (long)b * HWQ +
                         ((long)hh[mi * 2 + half] * Wd + ww[mi * 2 + half]) * (long)Q;
            #pragma unroll
            for (int ni = 0; ni < 4; ++ni) {
                float v0 = c[mi][ni][half * 2 + 0];
                float v1 = c[mi][ni][half * 2 + 1];
                float p0 = __shfl_xor_sync(0xFFFFFFFFu, v0, 1);
                float p1 = __shfl_xor_sync(0xFFFFFFFFu, v1, 1);
                if (ok && (lane & 1) == 0) {
                    int q = q0 + warp_n + ni * 8 + 2 * (lane & 3); // 0 or 4
                    if (q + 3 < Q) {
                        atomicAdd(reinterpret_cast<float4*>(out + obase + q),
                                  make_float4(v0, v1, p0, p1));
                    } else {
                        if (q     < Q) atomicAdd(out + obase + q,     v0);
                        if (q + 1 < Q) atomicAdd(out + obase + q + 1, v1);
                        if (q + 2 < Q) atomicAdd(out + obase + q + 2, p0);
                        if (q + 3 < Q) atomicAdd(out + obase + q + 3, p1);
                    }
                }
            }
        }
    }
}

// ---------------------------------------------------------------------------
static int isqrt_host(long v) {
    int r = (int)(sqrt((double)v) + 0.5);
    while ((long)r * r > v) --r;
    while ((long)(r + 1) * (r + 1) <= v) ++r;
    return r;
}

extern "C" void kernel_launch(void* const* d_in, const int* in_sizes, int n_in,
                              void* d_out, int out_size) {
    // Input order: queries, feature_values, feature_indices, query_batch_offsets,
    // feature_batch_offsets, height, width, W0,b0, W1,b1, W2,b2, W3,b3.
    const float* queries = (const float*)d_in[0];
    const float* fv      = (const float*)d_in[1];
    const int*   fidx    = (const int*)d_in[2];

    bool scalars_present = (n_in >= 15 && in_sizes[5] == 1 && in_sizes[6] == 1);
    int wbase = scalars_present ? 7 : 5;
    const int* width_ptr = scalars_present ? (const int*)d_in[6] : nullptr;

    const float* Wl[4];
    const float* bl[4];
    for (int i = 0; i < 4; ++i) {
        Wl[i] = (const float*)d_in[wbase + 2 * i];
        bl[i] = (const float*)d_in[wbase + 2 * i + 1];
    }

    const int D  = in_sizes[wbase + 1];       // len(b0)
    const int Mq = in_sizes[0] / D;           // B*Q
    const int B  = in_sizes[3] - 1;
    const int Q  = Mq / B;
    const int NF = in_sizes[1] / D;           // B*F
    const int F  = NF / B;
    const long HWQ = (long)out_size / B;      // H*W*Q
    const int width_imm = isqrt_host(HWQ / Q);

    float *buf0 = nullptr, *buf1 = nullptr;
    __half *fv_h = nullptr, *q_h = nullptr;
    cudaGetSymbolAddress((void**)&buf0, g_mlp_a);
    cudaGetSymbolAddress((void**)&buf1, g_mlp_b);
    cudaGetSymbolAddress((void**)&fv_h, g_fv_h);
    cudaGetSymbolAddress((void**)&q_h, g_q_h);

    // One-time setup (no device work; deterministic across calls)
    static cudaStream_t side1 = nullptr, side2 = nullptr;
    static cudaEvent_t ev_fork = nullptr, ev_j1 = nullptr, ev_j2 = nullptr;
    static bool attr_done = false;
    if (!side1) {
        cudaStreamCreateWithFlags(&side1, cudaStreamNonBlocking);
        cudaStreamCreateWithFlags(&side2, cudaStreamNonBlocking);
        cudaEventCreateWithFlags(&ev_fork, cudaEventDisableTiming);
        cudaEventCreateWithFlags(&ev_j1, cudaEventDisableTiming);
        cudaEventCreateWithFlags(&ev_j2, cudaEventDisableTiming);
    }
    if (!attr_done) {
        cudaFuncSetAttribute(logits_mma_kernel,
                             cudaFuncAttributeMaxDynamicSharedMemorySize,
                             LOGITS_SMEM);
        attr_done = true;
    }

    // ---- fork: side1 converts fv -> fp16; side2 zeroes output; main: MLP ----
    cudaEventRecord(ev_fork, 0);
    cudaStreamWaitEvent(side1, ev_fork, 0);
    cudaStreamWaitEvent(side2, ev_fork, 0);

    {
        long n4 = (long)NF * D / 4;
        convert_half_kernel<<<(int)DIV_UP(n4, 256L), 256, 0, side1>>>(fv, fv_h, n4);
    }
    cudaMemsetAsync(d_out, 0, (size_t)out_size * sizeof(float), side2);

    // main stream: 3x (linear+relu), final layer fused with fp16 store
    {
        dim3 grid(DIV_UP(Mq, 16), DIV_UP(D, 32));
        mlp_kernel<1, 0><<<grid, 128>>>(queries, Wl[0], bl[0], buf0, nullptr,
                                        Mq, D, D);
        mlp_kernel<1, 0><<<grid, 128>>>(buf0, Wl[1], bl[1], buf1, nullptr,
                                        Mq, D, D);
        mlp_kernel<1, 0><<<grid, 128>>>(buf1, Wl[2], bl[2], buf0, nullptr,
                                        Mq, D, D);
        mlp_kernel<0, 1><<<grid, 128>>>(buf0, Wl[3], bl[3], nullptr, q_h,
                                        Mq, D, D);
    }

    // ---- join ----
    cudaEventRecord(ev_j1, side1);
    cudaEventRecord(ev_j2, side2);
    cudaStreamWaitEvent(0, ev_j1, 0);
    cudaStreamWaitEvent(0, ev_j2, 0);

    // Logits GEMM (single-pass fp16) fused with scatter-add
    {
        dim3 grid(DIV_UP(Q, QTILE), DIV_UP(F, FTILE), B);
        logits_mma_kernel<<<grid, 256, LOGITS_SMEM>>>(fv_h, q_h, fidx,
                                                      (float*)d_out,
                                                      width_ptr, width_imm,
                                                      F, Q, D, HWQ);
    }
}

// round 10
// speedup vs baseline: 1.7544x; 1.0930x over previous
#include <cuda_runtime.h>
#include <cuda_bf16.h>
#include <cuda_fp16.h>
#include <cstdint>
#include <cmath>

#define DIV_UP(a, b) (((a) + (b) - 1) / (b))

// Scratch (static device allocations — the only legal kind here)
__device__ __align__(16) float g_mlp_a[1 << 20];     // 4 MB
__device__ __align__(16) float g_mlp_b[1 << 20];     // 4 MB
__device__ __align__(16) __half g_fv_h[1 << 24];     // 33.5 MB, fp16 fv
__device__ __align__(16) __half g_q_h[1 << 19];      // 1 MB, fp16 q

// ============================================================================
// helpers
// ============================================================================
__device__ __forceinline__ uint32_t smem_to_u32(const void* smem_ptr) {
    uint32_t addr;
    asm("{ .reg .u64 tmp; cvta.to.shared.u64 tmp, %1; cvt.u32.u64 %0, tmp; }"
        : "=r"(addr) : "l"(smem_ptr));
    return addr;
}

__device__ __forceinline__ void ldmatrix_x4(uint32_t* r, uint32_t addr) {
    asm volatile("ldmatrix.sync.aligned.m8n8.x4.shared.b16 {%0,%1,%2,%3}, [%4];"
                 : "=r"(r[0]), "=r"(r[1]), "=r"(r[2]), "=r"(r[3]) : "r"(addr));
}

// D += A(f16) * B(f16)^T, m16n8k16, fp32 accumulate
__device__ __forceinline__ void mma_f16(float* c, const uint32_t* a,
                                        const uint32_t* b) {
    asm volatile(
        "mma.sync.aligned.m16n8k16.row.col.f32.f16.f16.f32 "
        "{%0,%1,%2,%3}, {%4,%5,%6,%7}, {%8,%9}, {%0,%1,%2,%3};"
        : "+f"(c[0]), "+f"(c[1]), "+f"(c[2]), "+f"(c[3])
        : "r"(a[0]), "r"(a[1]), "r"(a[2]), "r"(a[3]), "r"(b[0]), "r"(b[1]));
}

__device__ __forceinline__ void cp16(uint32_t smem, const void* g) {
    asm volatile("cp.async.cg.shared.global [%0], [%1], 16;"
                 :: "r"(smem), "l"(g));
}

// ============================================================================
// fp32 -> fp16 (one streaming pass, round-to-nearest)
// ============================================================================
__global__ void __launch_bounds__(256)
convert_half_kernel(const float* __restrict__ in, __half* __restrict__ outp,
                    long n4) {
    long i = (long)blockIdx.x * blockDim.x + threadIdx.x;
    if (i >= n4) return;
    float4 v = reinterpret_cast<const float4*>(in)[i];
    __half2 h0 = __floats2half2_rn(v.x, v.y);
    __half2 h1 = __floats2half2_rn(v.z, v.w);
    reinterpret_cast<__half2*>(outp)[2 * i + 0] = h0;
    reinterpret_cast<__half2*>(outp)[2 * i + 1] = h1;
}

// ============================================================================
// MLP layer v2: Y[M,N] = act(X[M,K] @ W[N,K]^T + bias).
// BM=16, BN=32, BK = FULL K. One cp.async load phase, ONE sync, then a pure
// FMA loop. Natural row-major smem (k-contiguous) -> no transpose needed.
// 4 CTAs/SM via dynamic smem. SPLIT=1: final layer writes fp16 (no relu).
// ============================================================================
template <int RELU, int SPLIT>
__global__ void __launch_bounds__(128)
mlp_kernel(const float* __restrict__ X, const float* __restrict__ Wm,
           const float* __restrict__ bias, float* __restrict__ Y,
           __half* __restrict__ Yh, int M, int K, int N) {
    extern __shared__ __align__(16) float sm[];
    const int LDK = K + 4;                    // float stride per row
    float* Xs = sm;                           // [16][LDK]
    float* Ws = sm + 16 * LDK;                // [32][LDK]

    const int m0 = blockIdx.x * 16;
    const int n0 = blockIdx.y * 32;
    const int tid = threadIdx.x;
    const int ti = tid & 15;     // row 0..15
    const int tj = tid >> 4;     // col group 0..7 (4 cols each)

    const uint32_t xs_u = smem_to_u32(Xs);
    const uint32_t ws_u = smem_to_u32(Ws);

    // ---- load phase: X tile 16xK, W tile 32xK, all via cp.async ----
    const int xf4 = 16 * (K / 4);             // float4 count for X tile
    const int wf4 = 32 * (K / 4);
    const int kq  = K / 4;                    // float4 per row
    for (int idx = tid; idx < xf4; idx += 128) {
        int row = idx / kq, ks = (idx % kq) * 4;
        int m = m0 + row; if (m >= M) m = M - 1;   // clamp (harmless dup read)
        cp16(xs_u + (uint32_t)((row * LDK + ks) * 4), X + (long)m * K + ks);
    }
    for (int idx = tid; idx < wf4; idx += 128) {
        int row = idx / kq, ks = (idx % kq) * 4;
        cp16(ws_u + (uint32_t)((row * LDK + ks) * 4), Wm + (long)(n0 + row) * K + ks);
    }
    asm volatile("cp.async.commit_group;" ::: "memory");
    asm volatile("cp.async.wait_group 0;" ::: "memory");
    __syncthreads();

    // ---- compute: 4 outputs per thread (row ti, cols n0+tj*4 .. +3) ----
    float acc0 = 0.f, acc1 = 0.f, acc2 = 0.f, acc3 = 0.f;
    const float4* xrow = reinterpret_cast<const float4*>(Xs + ti * LDK);
    const float4* w0 = reinterpret_cast<const float4*>(Ws + (tj * 4 + 0) * LDK);
    const float4* w1 = reinterpret_cast<const float4*>(Ws + (tj * 4 + 1) * LDK);
    const float4* w2 = reinterpret_cast<const float4*>(Ws + (tj * 4 + 2) * LDK);
    const float4* w3 = reinterpret_cast<const float4*>(Ws + (tj * 4 + 3) * LDK);
    #pragma unroll 8
    for (int k4 = 0; k4 < K / 4; ++k4) {
        float4 xv = xrow[k4];
        float4 a = w0[k4];
        acc0 = fmaf(xv.x, a.x, fmaf(xv.y, a.y, fmaf(xv.z, a.z, fmaf(xv.w, a.w, acc0))));
        float4 bV = w1[k4];
        acc1 = fmaf(xv.x, bV.x, fmaf(xv.y, bV.y, fmaf(xv.z, bV.z, fmaf(xv.w, bV.w, acc1))));
        float4 cV = w2[k4];
        acc2 = fmaf(xv.x, cV.x, fmaf(xv.y, cV.y, fmaf(xv.z, cV.z, fmaf(xv.w, cV.w, acc2))));
        float4 dV = w3[k4];
        acc3 = fmaf(xv.x, dV.x, fmaf(xv.y, dV.y, fmaf(xv.z, dV.z, fmaf(xv.w, dV.w, acc3))));
    }

    const int m = m0 + ti;
    if (m >= M) return;
    const int n = n0 + tj * 4;
    float v0 = acc0 + bias[n + 0];
    float v1 = acc1 + bias[n + 1];
    float v2 = acc2 + bias[n + 2];
    float v3 = acc3 + bias[n + 3];
    if (SPLIT) {
        __half2* dst = reinterpret_cast<__half2*>(Yh + (long)m * N + n);
        dst[0] = __floats2half2_rn(v0, v1);
        dst[1] = __floats2half2_rn(v2, v3);
    } else {
        if (RELU) {
            v0 = fmaxf(v0, 0.f); v1 = fmaxf(v1, 0.f);
            v2 = fmaxf(v2, 0.f); v3 = fmaxf(v3, 0.f);
        }
        *reinterpret_cast<float4*>(Y + (long)m * N + n) = make_float4(v0, v1, v2, v3);
    }
}

// ============================================================================
// Logits GEMM: single-pass fp16 m16n8k16, cp.async double-buffered,
// float4 vector-atomic scatter epilogue. (unchanged from R9 — proven)
// CTA tile: 128(f) x 64(q), 8 warps 4x2, warp tile 32x32. 3 CTAs/SM.
// ============================================================================
constexpr int FTILE = 128;
constexpr int QTILE = 64;
constexpr int KC    = 32;
constexpr int LDSA  = KC + 8;   // fp16 elems per smem row (80B stride)

constexpr int OFF_A = 0;
constexpr int OFF_B = OFF_A + FTILE * LDSA * 2;       // 10240
constexpr int BUF_SZ = OFF_B + QTILE * LDSA * 2;      // 15360
constexpr int LOGITS_SMEM = 2 * BUF_SZ;               // 30720

__global__ void __launch_bounds__(256, 3)
logits_mma_kernel(const __half* __restrict__ fv_h,   // [B*F, D] fp16
                  const __half* __restrict__ q_h,    // [B*Q, D] fp16
                  const int* __restrict__ fidx,      // [B*F, 3]
                  float* __restrict__ out,
                  const int* __restrict__ width_ptr, int width_imm,
                  int F, int Q, int D, long HWQ) {
    extern __shared__ __align__(16) char smem[];
    const uint32_t sbase = smem_to_u32(smem);

    const int tid  = threadIdx.x;
    const int wid  = tid >> 5;
    const int lane = tid & 31;
    const int b  = blockIdx.z;
    const int q0 = blockIdx.x * QTILE;   // q fastest -> A tiles reused in L2
    const int f0 = blockIdx.y * FTILE;

    const int warp_m = (wid & 3) * 32;
    const int warp_n = (wid >> 2) * 32;

    const long arow0 = (long)b * F + f0;
    const long brow0 = (long)b * Q;

    // ---- prefetch scatter indices for this thread's 4 output rows ----
    const int Wd = width_ptr ? *width_ptr : width_imm;
    int hh[4], ww[4];
    #pragma unroll
    for (int mi = 0; mi < 2; ++mi) {
        #pragma unroll
        for (int half = 0; half < 2; ++half) {
            int row = warp_m + mi * 16 + half * 8 + (lane >> 2);
            long n = arow0 + row;
            hh[mi * 2 + half] = fidx[3 * n + 1];
            ww[mi * 2 + half] = fidx[3 * n + 2];
        }
    }

    float c[2][4][4] = {};

    const int nch = D / KC;

    auto load_chunk = [&](int cc) {
        const int k0 = cc * KC;
        const uint32_t bb = sbase + (uint32_t)(cc & 1) * BUF_SZ;
        #pragma unroll
        for (int i = 0; i < 2; ++i) {
            int idx = tid + i * 256;
            int row = idx >> 2;           // 0..127
            int seg = (idx & 3) * 8;      // fp16 col 0,8,16,24
            long gg = (arow0 + row) * D + k0 + seg;
            uint32_t soff = (uint32_t)((row * LDSA + seg) * 2);
            cp16(bb + OFF_A + soff, fv_h + gg);
        }
        {
            int row = tid >> 2;           // 0..63
            int seg = (tid & 3) * 8;
            int q = q0 + row;
            if (q >= Q) q = Q - 1;        // clamp; masked in epilogue
            long gg = (brow0 + q) * D + k0 + seg;
            uint32_t soff = (uint32_t)((row * LDSA + seg) * 2);
            cp16(bb + OFF_B + soff, q_h + gg);
        }
        asm volatile("cp.async.commit_group;" ::: "memory");
    };

    load_chunk(0);

    for (int cc = 0; cc < nch; ++cc) {
        if (cc + 1 < nch) {
            load_chunk(cc + 1);
            asm volatile("cp.async.wait_group 1;" ::: "memory");
        } else {
            asm volatile("cp.async.wait_group 0;" ::: "memory");
        }
        __syncthreads();

        const uint32_t bb = sbase + (uint32_t)(cc & 1) * BUF_SZ;
        const uint32_t as = bb + OFF_A;
        const uint32_t bs = bb + OFF_B;

        #pragma unroll
        for (int kk = 0; kk < KC; kk += 16) {
            uint32_t a[2][4];
            #pragma unroll
            for (int mi = 0; mi < 2; ++mi) {
                int row = warp_m + mi * 16 + (lane & 15);
                int col = kk + ((lane >> 4) << 3);
                uint32_t addr = (uint32_t)((row * LDSA + col) * 2);
                ldmatrix_x4(a[mi], as + addr);
            }
            uint32_t bfr[4][2];
            #pragma unroll
            for (int nb = 0; nb < 2; ++nb) {
                int row = warp_n + nb * 16 + ((lane & 16) >> 1) + (lane & 7);
                int col = kk + ((lane >> 3) & 1) * 8;
                uint32_t addr = (uint32_t)((row * LDSA + col) * 2);
                uint32_t r[4];
                ldmatrix_x4(r, bs + addr);
                bfr[nb * 2 + 0][0] = r[0]; bfr[nb * 2 + 0][1] = r[1];
                bfr[nb * 2 + 1][0] = r[2]; bfr[nb * 2 + 1][1] = r[3];
            }
            #pragma unroll
            for (int mi = 0; mi < 2; ++mi) {
                #pragma unroll
                for (int ni = 0; ni < 4; ++ni) {
                    mma_f16(c[mi][ni], a[mi], bfr[ni]);
                }
            }
        }
        __syncthreads();
    }

    // ---- epilogue: lane-paired float4 vector atomics ----
    #pragma unroll
    for (int mi = 0; mi < 2; ++mi) {
        #pragma unroll
        for (int half = 0; half < 2; ++half) {
            int row = warp_m + mi * 16 + half * 8 + (lane >> 2);
            int f = f0 + row;
            bool ok = (f < F);
            long obase = (long)b * HWQ +
                         ((long)hh[mi * 2 + half] * Wd + ww[mi * 2 + half]) * (long)Q;
            #pragma unroll
            for (int ni = 0; ni < 4; ++ni) {
                float v0 = c[mi][ni][half * 2 + 0];
                float v1 = c[mi][ni][half * 2 + 1];
                float p0 = __shfl_xor_sync(0xFFFFFFFFu, v0, 1);
                float p1 = __shfl_xor_sync(0xFFFFFFFFu, v1, 1);
                if (ok && (lane & 1) == 0) {
                    int q = q0 + warp_n + ni * 8 + 2 * (lane & 3); // 0 or 4
                    if (q + 3 < Q) {
                        atomicAdd(reinterpret_cast<float4*>(out + obase + q),
                                  make_float4(v0, v1, p0, p1));
                    } else {
                        if (q     < Q) atomicAdd(out + obase + q,     v0);
                        if (q + 1 < Q) atomicAdd(out + obase + q + 1, v1);
                        if (q + 2 < Q) atomicAdd(out + obase + q + 2, p0);
                        if (q + 3 < Q) atomicAdd(out + obase + q + 3, p1);
                    }
                }
            }
        }
    }
}

// ---------------------------------------------------------------------------
static int isqrt_host(long v) {
    int r = (int)(sqrt((double)v) + 0.5);
    while ((long)r * r > v) --r;
    while ((long)(r + 1) * (r + 1) <= v) ++r;
    return r;
}

extern "C" void kernel_launch(void* const* d_in, const int* in_sizes, int n_in,
                              void* d_out, int out_size) {
    // Input order: queries, feature_values, feature_indices, query_batch_offsets,
    // feature_batch_offsets, height, width, W0,b0, W1,b1, W2,b2, W3,b3.
    const float* queries = (const float*)d_in[0];
    const float* fv      = (const float*)d_in[1];
    const int*   fidx    = (const int*)d_in[2];

    bool scalars_present = (n_in >= 15 && in_sizes[5] == 1 && in_sizes[6] == 1);
    int wbase = scalars_present ? 7 : 5;
    const int* width_ptr = scalars_present ? (const int*)d_in[6] : nullptr;

    const float* Wl[4];
    const float* bl[4];
    for (int i = 0; i < 4; ++i) {
        Wl[i] = (const float*)d_in[wbase + 2 * i];
        bl[i] = (const float*)d_in[wbase + 2 * i + 1];
    }

    const int D  = in_sizes[wbase + 1];       // len(b0)
    const int Mq = in_sizes[0] / D;           // B*Q
    const int B  = in_sizes[3] - 1;
    const int Q  = Mq / B;
    const int NF = in_sizes[1] / D;           // B*F
    const int F  = NF / B;
    const long HWQ = (long)out_size / B;      // H*W*Q
    const int width_imm = isqrt_host(HWQ / Q);
    const size_t mlp_smem = (size_t)48 * (D + 4) * 4;   // 16+32 rows x (D+4) fp32

    float *buf0 = nullptr, *buf1 = nullptr;
    __half *fv_h = nullptr, *q_h = nullptr;
    cudaGetSymbolAddress((void**)&buf0, g_mlp_a);
    cudaGetSymbolAddress((void**)&buf1, g_mlp_b);
    cudaGetSymbolAddress((void**)&fv_h, g_fv_h);
    cudaGetSymbolAddress((void**)&q_h, g_q_h);

    // One-time setup (no device work; deterministic across calls)
    static cudaStream_t side1 = nullptr, side2 = nullptr;
    static cudaEvent_t ev_fork = nullptr, ev_j1 = nullptr, ev_j2 = nullptr;
    static bool attr_done = false;
    if (!side1) {
        cudaStreamCreateWithFlags(&side1, cudaStreamNonBlocking);
        cudaStreamCreateWithFlags(&side2, cudaStreamNonBlocking);
        cudaEventCreateWithFlags(&ev_fork, cudaEventDisableTiming);
        cudaEventCreateWithFlags(&ev_j1, cudaEventDisableTiming);
        cudaEventCreateWithFlags(&ev_j2, cudaEventDisableTiming);
    }
    if (!attr_done) {
        cudaFuncSetAttribute(logits_mma_kernel,
                             cudaFuncAttributeMaxDynamicSharedMemorySize,
                             LOGITS_SMEM);
        cudaFuncSetAttribute(mlp_kernel<1, 0>,
                             cudaFuncAttributeMaxDynamicSharedMemorySize,
                             (int)mlp_smem);
        cudaFuncSetAttribute(mlp_kernel<0, 1>,
                             cudaFuncAttributeMaxDynamicSharedMemorySize,
                             (int)mlp_smem);
        attr_done = true;
    }

    // ---- fork: side1 converts fv -> fp16; side2 zeroes output; main: MLP ----
    cudaEventRecord(ev_fork, 0);
    cudaStreamWaitEvent(side1, ev_fork, 0);
    cudaStreamWaitEvent(side2, ev_fork, 0);

    {
        long n4 = (long)NF * D / 4;
        convert_half_kernel<<<(int)DIV_UP(n4, 256L), 256, 0, side1>>>(fv, fv_h, n4);
    }
    cudaMemsetAsync(d_out, 0, (size_t)out_size * sizeof(float), side2);

    // main stream: 3x (linear+relu), final layer fused with fp16 store
    {
        dim3 grid(DIV_UP(Mq, 16), DIV_UP(D, 32));
        mlp_kernel<1, 0><<<grid, 128, mlp_smem>>>(queries, Wl[0], bl[0], buf0,
                                                  nullptr, Mq, D, D);
        mlp_kernel<1, 0><<<grid, 128, mlp_smem>>>(buf0, Wl[1], bl[1], buf1,
                                                  nullptr, Mq, D, D);
        mlp_kernel<1, 0><<<grid, 128, mlp_smem>>>(buf1, Wl[2], bl[2], buf0,
                                                  nullptr, Mq, D, D);
        mlp_kernel<0, 1><<<grid, 128, mlp_smem>>>(buf0, Wl[3], bl[3], nullptr,
                                                  q_h, Mq, D, D);
    }

    // ---- join ----
    cudaEventRecord(ev_j1, side1);
    cudaEventRecord(ev_j2, side2);
    cudaStreamWaitEvent(0, ev_j1, 0);
    cudaStreamWaitEvent(0, ev_j2, 0);

    // Logits GEMM (single-pass fp16) fused with scatter-add
    {
        dim3 grid(DIV_UP(Q, QTILE), DIV_UP(F, FTILE), B);
        logits_mma_kernel<<<grid, 256, LOGITS_SMEM>>>(fv_h, q_h, fidx,
                                                      (float*)d_out,
                                                      width_ptr, width_imm,
                                                      F, Q, D, HWQ);
    }
}

// round 11
// speedup vs baseline: 1.7549x; 1.0002x over previous
#include <cuda_runtime.h>
#include <cuda_bf16.h>
#include <cuda_fp16.h>
#include <cstdint>
#include <cmath>

#define DIV_UP(a, b) (((a) + (b) - 1) / (b))

// Scratch (static device allocations — the only legal kind here)
__device__ __align__(16) __half g_fv_h[1 << 24];           // 33.5 MB fp16 fv
__device__ __align__(16) __half g_q_h[1 << 19];            // fp16 q (MLP out)
__device__ __align__(16) __nv_bfloat16 g_x0_hi[1 << 19];   // MLP act planes
__device__ __align__(16) __nv_bfloat16 g_x0_lo[1 << 19];
__device__ __align__(16) __nv_bfloat16 g_x1_hi[1 << 19];
__device__ __align__(16) __nv_bfloat16 g_x1_lo[1 << 19];
__device__ __align__(16) __nv_bfloat16 g_w_hi[1 << 18];    // 4 weight mats
__device__ __align__(16) __nv_bfloat16 g_w_lo[1 << 18];

// ============================================================================
// helpers
// ============================================================================
__device__ __forceinline__ uint32_t smem_to_u32(const void* smem_ptr) {
    uint32_t addr;
    asm("{ .reg .u64 tmp; cvta.to.shared.u64 tmp, %1; cvt.u32.u64 %0, tmp; }"
        : "=r"(addr) : "l"(smem_ptr));
    return addr;
}

__device__ __forceinline__ void ldmatrix_x4(uint32_t* r, uint32_t addr) {
    asm volatile("ldmatrix.sync.aligned.m8n8.x4.shared.b16 {%0,%1,%2,%3}, [%4];"
                 : "=r"(r[0]), "=r"(r[1]), "=r"(r[2]), "=r"(r[3]) : "r"(addr));
}

// D += A(f16) * B(f16)^T, m16n8k16, fp32 accumulate
__device__ __forceinline__ void mma_f16(float* c, const uint32_t* a,
                                        const uint32_t* b) {
    asm volatile(
        "mma.sync.aligned.m16n8k16.row.col.f32.f16.f16.f32 "
        "{%0,%1,%2,%3}, {%4,%5,%6,%7}, {%8,%9}, {%0,%1,%2,%3};"
        : "+f"(c[0]), "+f"(c[1]), "+f"(c[2]), "+f"(c[3])
        : "r"(a[0]), "r"(a[1]), "r"(a[2]), "r"(a[3]), "r"(b[0]), "r"(b[1]));
}

// D += A(bf16) * B(bf16)^T, m16n8k16, fp32 accumulate
__device__ __forceinline__ void mma_bf16(float* c, const uint32_t* a,
                                         const uint32_t* b) {
    asm volatile(
        "mma.sync.aligned.m16n8k16.row.col.f32.bf16.bf16.f32 "
        "{%0,%1,%2,%3}, {%4,%5,%6,%7}, {%8,%9}, {%0,%1,%2,%3};"
        : "+f"(c[0]), "+f"(c[1]), "+f"(c[2]), "+f"(c[3])
        : "r"(a[0]), "r"(a[1]), "r"(a[2]), "r"(a[3]), "r"(b[0]), "r"(b[1]));
}

__device__ __forceinline__ void cp16(uint32_t smem, const void* g) {
    asm volatile("cp.async.cg.shared.global [%0], [%1], 16;"
                 :: "r"(smem), "l"(g));
}

// split fp32 pair into packed bf16x2 hi and lo planes
__device__ __forceinline__ void split2(float x, float y, uint32_t& hi, uint32_t& lo) {
    __nv_bfloat16 hx = __float2bfloat16(x);
    __nv_bfloat16 hy = __float2bfloat16(y);
    __nv_bfloat16 lx = __float2bfloat16(x - __bfloat162float(hx));
    __nv_bfloat16 ly = __float2bfloat16(y - __bfloat162float(hy));
    hi = (uint32_t)__bfloat16_as_ushort(hx) | ((uint32_t)__bfloat16_as_ushort(hy) << 16);
    lo = (uint32_t)__bfloat16_as_ushort(lx) | ((uint32_t)__bfloat16_as_ushort(ly) << 16);
}

// ============================================================================
// conversion kernels
// ============================================================================
__global__ void __launch_bounds__(256)
convert_half_kernel(const float* __restrict__ in, __half* __restrict__ outp,
                    long n4) {
    long i = (long)blockIdx.x * blockDim.x + threadIdx.x;
    if (i >= n4) return;
    float4 v = reinterpret_cast<const float4*>(in)[i];
    reinterpret_cast<__half2*>(outp)[2 * i + 0] = __floats2half2_rn(v.x, v.y);
    reinterpret_cast<__half2*>(outp)[2 * i + 1] = __floats2half2_rn(v.z, v.w);
}

__global__ void __launch_bounds__(256)
convert_split_kernel(const float* __restrict__ in,
                     __nv_bfloat16* __restrict__ hi,
                     __nv_bfloat16* __restrict__ lo, long n4) {
    long i = (long)blockIdx.x * blockDim.x + threadIdx.x;
    if (i >= n4) return;
    float4 v = reinterpret_cast<const float4*>(in)[i];
    uint32_t h0, l0, h1, l1;
    split2(v.x, v.y, h0, l0);
    split2(v.z, v.w, h1, l1);
    reinterpret_cast<uint2*>(hi)[i] = make_uint2(h0, h1);
    reinterpret_cast<uint2*>(lo)[i] = make_uint2(l0, l1);
}

// ============================================================================
// MLP layer via tensor cores: Y = act(X @ W^T + bias), bf16 hi/lo 3-term.
// CTA 64(m)x64(n), 4 warps 2x2, warp tile 32x32, KC=64 double-buffered.
// LAST=1: writes fp16 q_h (no relu); else writes bf16 hi/lo act planes.
// ============================================================================
constexpr int MKC   = 64;
constexpr int MLDS  = MKC + 8;                       // bf16 stride (144B)
constexpr int M_A_HI = 0;
constexpr int M_A_LO = M_A_HI + 64 * MLDS * 2;       // 9216
constexpr int M_B_HI = M_A_LO + 64 * MLDS * 2;       // 18432
constexpr int M_B_LO = M_B_HI + 64 * MLDS * 2;       // 27648
constexpr int M_BUF  = M_B_LO + 64 * MLDS * 2;       // 36864
constexpr int MLP_SMEM = 2 * M_BUF;                  // 73728

template <int RELU, int LAST>
__global__ void __launch_bounds__(128)
mlp_mma_kernel(const __nv_bfloat16* __restrict__ x_hi,
               const __nv_bfloat16* __restrict__ x_lo,
               const __nv_bfloat16* __restrict__ w_hi,
               const __nv_bfloat16* __restrict__ w_lo,
               const float* __restrict__ bias,
               __nv_bfloat16* __restrict__ y_hi,
               __nv_bfloat16* __restrict__ y_lo,
               __half* __restrict__ yh,
               int M, int K, int N) {
    extern __shared__ __align__(16) char smem[];
    const uint32_t sbase = smem_to_u32(smem);

    const int tid  = threadIdx.x;
    const int wid  = tid >> 5;
    const int lane = tid & 31;
    const int n0 = blockIdx.x * 64;
    const int m0 = blockIdx.y * 64;

    const int warp_m = (wid & 1) * 32;
    const int warp_n = (wid >> 1) * 32;

    float c[2][4][4] = {};

    const int nch = K / MKC;

    auto load_chunk = [&](int cc) {
        const int k0 = cc * MKC;
        const uint32_t bb = sbase + (uint32_t)(cc & 1) * M_BUF;
        // A planes: 64 rows x 64 bf16 = 512 x 16B each
        #pragma unroll
        for (int i = 0; i < 4; ++i) {
            int idx = tid + i * 128;
            int row = idx >> 3;            // 0..63
            int seg = (idx & 7) * 8;       // bf16 col
            int m = m0 + row; if (m >= M) m = M - 1;
            long gg = (long)m * K + k0 + seg;
            uint32_t soff = (uint32_t)((row * MLDS + seg) * 2);
            cp16(bb + M_A_HI + soff, x_hi + gg);
            cp16(bb + M_A_LO + soff, x_lo + gg);
        }
        // B planes: 64 rows x 64 bf16
        #pragma unroll
        for (int i = 0; i < 4; ++i) {
            int idx = tid + i * 128;
            int row = idx >> 3;
            int seg = (idx & 7) * 8;
            long gg = (long)(n0 + row) * K + k0 + seg;
            uint32_t soff = (uint32_t)((row * MLDS + seg) * 2);
            cp16(bb + M_B_HI + soff, w_hi + gg);
            cp16(bb + M_B_LO + soff, w_lo + gg);
        }
        asm volatile("cp.async.commit_group;" ::: "memory");
    };

    load_chunk(0);

    for (int cc = 0; cc < nch; ++cc) {
        if (cc + 1 < nch) {
            load_chunk(cc + 1);
            asm volatile("cp.async.wait_group 1;" ::: "memory");
        } else {
            asm volatile("cp.async.wait_group 0;" ::: "memory");
        }
        __syncthreads();

        const uint32_t bb = sbase + (uint32_t)(cc & 1) * M_BUF;
        const uint32_t ah_s = bb + M_A_HI;
        const uint32_t al_s = bb + M_A_LO;
        const uint32_t bh_s = bb + M_B_HI;
        const uint32_t bl_s = bb + M_B_LO;

        #pragma unroll
        for (int kk = 0; kk < MKC; kk += 16) {
            uint32_t ah[2][4], al[2][4];
            #pragma unroll
            for (int mi = 0; mi < 2; ++mi) {
                int row = warp_m + mi * 16 + (lane & 15);
                int col = kk + ((lane >> 4) << 3);
                uint32_t addr = (uint32_t)((row * MLDS + col) * 2);
                ldmatrix_x4(ah[mi], ah_s + addr);
                ldmatrix_x4(al[mi], al_s + addr);
            }
            uint32_t bh[4][2], bl[4][2];
            #pragma unroll
            for (int nb = 0; nb < 2; ++nb) {
                int row = warp_n + nb * 16 + ((lane & 16) >> 1) + (lane & 7);
                int col = kk + ((lane >> 3) & 1) * 8;
                uint32_t addr = (uint32_t)((row * MLDS + col) * 2);
                uint32_t rh[4], rl[4];
                ldmatrix_x4(rh, bh_s + addr);
                ldmatrix_x4(rl, bl_s + addr);
                bh[nb * 2 + 0][0] = rh[0]; bh[nb * 2 + 0][1] = rh[1];
                bh[nb * 2 + 1][0] = rh[2]; bh[nb * 2 + 1][1] = rh[3];
                bl[nb * 2 + 0][0] = rl[0]; bl[nb * 2 + 0][1] = rl[1];
                bl[nb * 2 + 1][0] = rl[2]; bl[nb * 2 + 1][1] = rl[3];
            }
            #pragma unroll
            for (int mi = 0; mi < 2; ++mi) {
                #pragma unroll
                for (int ni = 0; ni < 4; ++ni) {
                    mma_bf16(c[mi][ni], ah[mi], bh[ni]);   // hi*hi
                    mma_bf16(c[mi][ni], ah[mi], bl[ni]);   // hi*lo
                    mma_bf16(c[mi][ni], al[mi], bh[ni]);   // lo*hi
                }
            }
        }
        __syncthreads();
    }

    // ---- epilogue: bias (+relu), emit bf16 hi/lo planes or fp16 ----
    #pragma unroll
    for (int mi = 0; mi < 2; ++mi) {
        #pragma unroll
        for (int half = 0; half < 2; ++half) {
            int m = m0 + warp_m + mi * 16 + half * 8 + (lane >> 2);
            if (m >= M) continue;
            #pragma unroll
            for (int ni = 0; ni < 4; ++ni) {
                int n = n0 + warp_n + ni * 8 + 2 * (lane & 3);
                float v0 = c[mi][ni][half * 2 + 0] + bias[n];
                float v1 = c[mi][ni][half * 2 + 1] + bias[n + 1];
                if (LAST) {
                    *reinterpret_cast<__half2*>(yh + (long)m * N + n) =
                        __floats2half2_rn(v0, v1);
                } else {
                    if (RELU) { v0 = fmaxf(v0, 0.f); v1 = fmaxf(v1, 0.f); }
                    uint32_t h, l;
                    split2(v0, v1, h, l);
                    long o = ((long)m * N + n) >> 1;
                    reinterpret_cast<uint32_t*>(y_hi)[o] = h;
                    reinterpret_cast<uint32_t*>(y_lo)[o] = l;
                }
            }
        }
    }
}

// ============================================================================
// Logits GEMM: single-pass fp16 m16n8k16, cp.async double-buffered,
// float4 vector-atomic scatter epilogue. (unchanged from R9/R10 — proven)
// CTA tile: 128(f) x 64(q), 8 warps 4x2, warp tile 32x32. 3 CTAs/SM.
// ============================================================================
constexpr int FTILE = 128;
constexpr int QTILE = 64;
constexpr int KC    = 32;
constexpr int LDSA  = KC + 8;   // fp16 elems per smem row (80B stride)

constexpr int OFF_A = 0;
constexpr int OFF_B = OFF_A + FTILE * LDSA * 2;       // 10240
constexpr int BUF_SZ = OFF_B + QTILE * LDSA * 2;      // 15360
constexpr int LOGITS_SMEM = 2 * BUF_SZ;               // 30720

__global__ void __launch_bounds__(256, 3)
logits_mma_kernel(const __half* __restrict__ fv_h,   // [B*F, D] fp16
                  const __half* __restrict__ q_h,    // [B*Q, D] fp16
                  const int* __restrict__ fidx,      // [B*F, 3]
                  float* __restrict__ out,
                  const int* __restrict__ width_ptr, int width_imm,
                  int F, int Q, int D, long HWQ) {
    extern __shared__ __align__(16) char smem[];
    const uint32_t sbase = smem_to_u32(smem);

    const int tid  = threadIdx.x;
    const int wid  = tid >> 5;
    const int lane = tid & 31;
    const int b  = blockIdx.z;
    const int q0 = blockIdx.x * QTILE;   // q fastest -> A tiles reused in L2
    const int f0 = blockIdx.y * FTILE;

    const int warp_m = (wid & 3) * 32;
    const int warp_n = (wid >> 2) * 32;

    const long arow0 = (long)b * F + f0;
    const long brow0 = (long)b * Q;

    // ---- prefetch scatter indices for this thread's 4 output rows ----
    const int Wd = width_ptr ? *width_ptr : width_imm;
    int hh[4], ww[4];
    #pragma unroll
    for (int mi = 0; mi < 2; ++mi) {
        #pragma unroll
        for (int half = 0; half < 2; ++half) {
            int row = warp_m + mi * 16 + half * 8 + (lane >> 2);
            long n = arow0 + row;
            hh[mi * 2 + half] = fidx[3 * n + 1];
            ww[mi * 2 + half] = fidx[3 * n + 2];
        }
    }

    float c[2][4][4] = {};

    const int nch = D / KC;

    auto load_chunk = [&](int cc) {
        const int k0 = cc * KC;
        const uint32_t bb = sbase + (uint32_t)(cc & 1) * BUF_SZ;
        #pragma unroll
        for (int i = 0; i < 2; ++i) {
            int idx = tid + i * 256;
            int row = idx >> 2;           // 0..127
            int seg = (idx & 3) * 8;      // fp16 col 0,8,16,24
            long gg = (arow0 + row) * D + k0 + seg;
            uint32_t soff = (uint32_t)((row * LDSA + seg) * 2);
            cp16(bb + OFF_A + soff, fv_h + gg);
        }
        {
            int row = tid >> 2;           // 0..63
            int seg = (tid & 3) * 8;
            int q = q0 + row;
            if (q >= Q) q = Q - 1;        // clamp; masked in epilogue
            long gg = (brow0 + q) * D + k0 + seg;
            uint32_t soff = (uint32_t)((row * LDSA + seg) * 2);
            cp16(bb + OFF_B + soff, q_h + gg);
        }
        asm volatile("cp.async.commit_group;" ::: "memory");
    };

    load_chunk(0);

    for (int cc = 0; cc < nch; ++cc) {
        if (cc + 1 < nch) {
            load_chunk(cc + 1);
            asm volatile("cp.async.wait_group 1;" ::: "memory");
        } else {
            asm volatile("cp.async.wait_group 0;" ::: "memory");
        }
        __syncthreads();

        const uint32_t bb = sbase + (uint32_t)(cc & 1) * BUF_SZ;
        const uint32_t as = bb + OFF_A;
        const uint32_t bs = bb + OFF_B;

        #pragma unroll
        for (int kk = 0; kk < KC; kk += 16) {
            uint32_t a[2][4];
            #pragma unroll
            for (int mi = 0; mi < 2; ++mi) {
                int row = warp_m + mi * 16 + (lane & 15);
                int col = kk + ((lane >> 4) << 3);
                uint32_t addr = (uint32_t)((row * LDSA + col) * 2);
                ldmatrix_x4(a[mi], as + addr);
            }
            uint32_t bfr[4][2];
            #pragma unroll
            for (int nb = 0; nb < 2; ++nb) {
                int row = warp_n + nb * 16 + ((lane & 16) >> 1) + (lane & 7);
                int col = kk + ((lane >> 3) & 1) * 8;
                uint32_t addr = (uint32_t)((row * LDSA + col) * 2);
                uint32_t r[4];
                ldmatrix_x4(r, bs + addr);
                bfr[nb * 2 + 0][0] = r[0]; bfr[nb * 2 + 0][1] = r[1];
                bfr[nb * 2 + 1][0] = r[2]; bfr[nb * 2 + 1][1] = r[3];
            }
            #pragma unroll
            for (int mi = 0; mi < 2; ++mi) {
                #pragma unroll
                for (int ni = 0; ni < 4; ++ni) {
                    mma_f16(c[mi][ni], a[mi], bfr[ni]);
                }
            }
        }
        __syncthreads();
    }

    // ---- epilogue: lane-paired float4 vector atomics ----
    #pragma unroll
    for (int mi = 0; mi < 2; ++mi) {
        #pragma unroll
        for (int half = 0; half < 2; ++half) {
            int row = warp_m + mi * 16 + half * 8 + (lane >> 2);
            int f = f0 + row;
            bool ok = (f < F);
            long obase = (long)b * HWQ +
                         ((long)hh[mi * 2 + half] * Wd + ww[mi * 2 + half]) * (long)Q;
            #pragma unroll
            for (int ni = 0; ni < 4; ++ni) {
                float v0 = c[mi][ni][half * 2 + 0];
                float v1 = c[mi][ni][half * 2 + 1];
                float p0 = __shfl_xor_sync(0xFFFFFFFFu, v0, 1);
                float p1 = __shfl_xor_sync(0xFFFFFFFFu, v1, 1);
                if (ok && (lane & 1) == 0) {
                    int q = q0 + warp_n + ni * 8 + 2 * (lane & 3); // 0 or 4
                    if (q + 3 < Q) {
                        atomicAdd(reinterpret_cast<float4*>(out + obase + q),
                                  make_float4(v0, v1, p0, p1));
                    } else {
                        if (q     < Q) atomicAdd(out + obase + q,     v0);
                        if (q + 1 < Q) atomicAdd(out + obase + q + 1, v1);
                        if (q + 2 < Q) atomicAdd(out + obase + q + 2, p0);
                        if (q + 3 < Q) atomicAdd(out + obase + q + 3, p1);
                    }
                }
            }
        }
    }
}

// ---------------------------------------------------------------------------
static int isqrt_host(long v) {
    int r = (int)(sqrt((double)v) + 0.5);
    while ((long)r * r > v) --r;
    while ((long)(r + 1) * (r + 1) <= v) ++r;
    return r;
}

extern "C" void kernel_launch(void* const* d_in, const int* in_sizes, int n_in,
                              void* d_out, int out_size) {
    // Input order: queries, feature_values, feature_indices, query_batch_offsets,
    // feature_batch_offsets, height, width, W0,b0, W1,b1, W2,b2, W3,b3.
    const float* queries = (const float*)d_in[0];
    const float* fv      = (const float*)d_in[1];
    const int*   fidx    = (const int*)d_in[2];

    bool scalars_present = (n_in >= 15 && in_sizes[5] == 1 && in_sizes[6] == 1);
    int wbase = scalars_present ? 7 : 5;
    const int* width_ptr = scalars_present ? (const int*)d_in[6] : nullptr;

    const float* Wl[4];
    const float* bl[4];
    for (int i = 0; i < 4; ++i) {
        Wl[i] = (const float*)d_in[wbase + 2 * i];
        bl[i] = (const float*)d_in[wbase + 2 * i + 1];
    }

    const int D  = in_sizes[wbase + 1];       // len(b0)
    const int Mq = in_sizes[0] / D;           // B*Q
    const int B  = in_sizes[3] - 1;
    const int Q  = Mq / B;
    const int NF = in_sizes[1] / D;           // B*F
    const int F  = NF / B;
    const long HWQ = (long)out_size / B;      // H*W*Q
    const int width_imm = isqrt_host(HWQ / Q);

    __half *fv_h = nullptr, *q_h = nullptr;
    __nv_bfloat16 *x0h = nullptr, *x0l = nullptr, *x1h = nullptr, *x1l = nullptr;
    __nv_bfloat16 *wh = nullptr, *wl = nullptr;
    cudaGetSymbolAddress((void**)&fv_h, g_fv_h);
    cudaGetSymbolAddress((void**)&q_h, g_q_h);
    cudaGetSymbolAddress((void**)&x0h, g_x0_hi);
    cudaGetSymbolAddress((void**)&x0l, g_x0_lo);
    cudaGetSymbolAddress((void**)&x1h, g_x1_hi);
    cudaGetSymbolAddress((void**)&x1l, g_x1_lo);
    cudaGetSymbolAddress((void**)&wh, g_w_hi);
    cudaGetSymbolAddress((void**)&wl, g_w_lo);

    // One-time setup (no device work; deterministic across calls)
    static cudaStream_t side1 = nullptr, side2 = nullptr;
    static cudaEvent_t ev_fork = nullptr, ev_w = nullptr, ev_j1 = nullptr,
                       ev_j2 = nullptr;
    static bool attr_done = false;
    if (!side1) {
        cudaStreamCreateWithFlags(&side1, cudaStreamNonBlocking);
        cudaStreamCreateWithFlags(&side2, cudaStreamNonBlocking);
        cudaEventCreateWithFlags(&ev_fork, cudaEventDisableTiming);
        cudaEventCreateWithFlags(&ev_w, cudaEventDisableTiming);
        cudaEventCreateWithFlags(&ev_j1, cudaEventDisableTiming);
        cudaEventCreateWithFlags(&ev_j2, cudaEventDisableTiming);
    }
    if (!attr_done) {
        cudaFuncSetAttribute(logits_mma_kernel,
                             cudaFuncAttributeMaxDynamicSharedMemorySize,
                             LOGITS_SMEM);
        cudaFuncSetAttribute(mlp_mma_kernel<1, 0>,
                             cudaFuncAttributeMaxDynamicSharedMemorySize,
                             MLP_SMEM);
        cudaFuncSetAttribute(mlp_mma_kernel<0, 1>,
                             cudaFuncAttributeMaxDynamicSharedMemorySize,
                             MLP_SMEM);
        attr_done = true;
    }

    // ---- fork ----
    cudaEventRecord(ev_fork, 0);
    cudaStreamWaitEvent(side1, ev_fork, 0);
    cudaStreamWaitEvent(side2, ev_fork, 0);

    // side1: convert fv -> fp16 (the big one, ~25us)
    {
        long n4 = (long)NF * D / 4;
        convert_half_kernel<<<(int)DIV_UP(n4, 256L), 256, 0, side1>>>(fv, fv_h, n4);
    }
    // side2: split all 4 weight matrices, then memset output
    {
        long w4 = (long)D * D / 4;
        for (int i = 0; i < 4; ++i)
            convert_split_kernel<<<(int)DIV_UP(w4, 256L), 256, 0, side2>>>(
                Wl[i], wh + (long)i * D * D, wl + (long)i * D * D, w4);
        cudaEventRecord(ev_w, side2);
        cudaMemsetAsync(d_out, 0, (size_t)out_size * sizeof(float), side2);
        cudaEventRecord(ev_j2, side2);
    }

    // main: split queries, wait for weights, run 4 tensor-core MLP layers
    {
        long n4 = (long)Mq * D / 4;
        convert_split_kernel<<<(int)DIV_UP(n4, 256L), 256>>>(queries, x0h, x0l, n4);
    }
    cudaStreamWaitEvent(0, ev_w, 0);
    {
        dim3 grid(D / 64, DIV_UP(Mq, 64));
        long wsz = (long)D * D;
        mlp_mma_kernel<1, 0><<<grid, 128, MLP_SMEM>>>(
            x0h, x0l, wh + 0 * wsz, wl + 0 * wsz, bl[0], x1h, x1l, nullptr,
            Mq, D, D);
        mlp_mma_kernel<1, 0><<<grid, 128, MLP_SMEM>>>(
            x1h, x1l, wh + 1 * wsz, wl + 1 * wsz, bl[1], x0h, x0l, nullptr,
            Mq, D, D);
        mlp_mma_kernel<1, 0><<<grid, 128, MLP_SMEM>>>(
            x0h, x0l, wh + 2 * wsz, wl + 2 * wsz, bl[2], x1h, x1l, nullptr,
            Mq, D, D);
        mlp_mma_kernel<0, 1><<<grid, 128, MLP_SMEM>>>(
            x1h, x1l, wh + 3 * wsz, wl + 3 * wsz, bl[3], nullptr, nullptr, q_h,
            Mq, D, D);
    }

    // ---- join ----
    cudaEventRecord(ev_j1, side1);
    cudaStreamWaitEvent(0, ev_j1, 0);
    cudaStreamWaitEvent(0, ev_j2, 0);

    // Logits GEMM (single-pass fp16) fused with scatter-add
    {
        dim3 grid(DIV_UP(Q, QTILE), DIV_UP(F, FTILE), B);
        logits_mma_kernel<<<grid, 256, LOGITS_SMEM>>>(fv_h, q_h, fidx,
                                                      (float*)d_out,
                                                      width_ptr, width_imm,
                                                      F, Q, D, HWQ);
    }
}